// round 2
// baseline (speedup 1.0000x reference)
#include <cuda_runtime.h>
#include <math.h>

#define NG   128
#define PN   256
#define EPG  1024
#define NN   (NG*PN)     // 32768
#define NE   (NG*EPG)    // 131072
#define DD   128
#define OUTD 10

// ---------------- device scratch (static, no runtime alloc) ----------------
__device__ float g_x[NN*DD];
__device__ float g_h[NN*DD];
__device__ float g_nm[8*NN];              // [(r*4+c)*NN + n]
__device__ float g_eemb[NE*DD];
__device__ float g_aggbb[NN*DD];
__device__ float g_centx[2*NG*4*DD];      // [((r*NG+g)*4+c)*DD + d]
__device__ float g_aggbc[2*NG*4*DD];
__device__ float g_Wccraw[2*NG*16];
__device__ float g_maxplus;
__device__ float g_hcent[2*NG*4*DD];
__device__ float g_aggcb[2*NN*DD];        // [r*NN*DD + n*DD + d]
__device__ float g_Z[NN*DD];
__device__ float g_hbm[NN*DD];

// ---------------------------------------------------------------------------
// Generic 128-col GEMM: out = epi( A1@W1 [+ A2@W2] )
// block: 128 rows x 128 cols, 256 threads, 8x8 per-thread tile
// ---------------------------------------------------------------------------
__device__ __forceinline__ void mma_pass(const float* __restrict__ A, int K,
                                         const float* __restrict__ Ws,
                                         float* As, int row0, int tid,
                                         int tr, int tc, float acc[8][8]) {
    for (int k0 = 0; k0 < K; k0 += 16) {
        __syncthreads();
        for (int idx = tid; idx < 128*16; idx += 256) {
            int rr = idx >> 4, kk = idx & 15;
            As[rr*17 + kk] = A[(size_t)(row0 + rr) * K + k0 + kk];
        }
        __syncthreads();
#pragma unroll
        for (int kk = 0; kk < 16; kk++) {
            float a[8], w[8];
#pragma unroll
            for (int i = 0; i < 8; i++) a[i] = As[(tr + 16*i)*17 + kk];
#pragma unroll
            for (int j = 0; j < 8; j++) w[j] = Ws[(k0 + kk)*128 + tc + 16*j];
#pragma unroll
            for (int i = 0; i < 8; i++)
#pragma unroll
                for (int j = 0; j < 8; j++)
                    acc[i][j] = fmaf(a[i], w[j], acc[i][j]);
        }
    }
}

__global__ void gemm128(const float* __restrict__ A1,
                        const float* __restrict__ W1, int K1,
                        const float* __restrict__ A2,
                        const float* __restrict__ W2,
                        const float* __restrict__ bias,
                        const float* __restrict__ addC,
                        const float* __restrict__ prevC,
                        int relu_flag,
                        float* __restrict__ out) {
    extern __shared__ float sm[];
    float* Ws1 = sm;
    float* Ws2 = Ws1 + K1*128;
    int ws2n = (A2 != nullptr) ? 128*128 : 0;
    float* As  = Ws2 + ws2n;

    const int tid = threadIdx.x;
    const int tr = tid >> 4, tc = tid & 15;
    const int row0 = blockIdx.x * 128;

    for (int i = tid; i < K1*128; i += 256) Ws1[i] = W1[i];
    if (A2) for (int i = tid; i < 128*128; i += 256) Ws2[i] = W2[i];

    float acc[8][8];
#pragma unroll
    for (int i = 0; i < 8; i++)
#pragma unroll
        for (int j = 0; j < 8; j++) acc[i][j] = 0.f;

    mma_pass(A1, K1, Ws1, As, row0, tid, tr, tc, acc);
    if (A2) mma_pass(A2, 128, Ws2, As, row0, tid, tr, tc, acc);

#pragma unroll
    for (int i = 0; i < 8; i++) {
        int row = row0 + tr + 16*i;
#pragma unroll
        for (int j = 0; j < 8; j++) {
            int col = tc + 16*j;
            float v = acc[i][j];
            if (bias)  v += bias[col];
            if (addC)  v += addC[(size_t)row*128 + col];
            if (relu_flag) v = fmaxf(v, 0.f);
            if (prevC) v = 0.5f * (prevC[(size_t)row*128 + col] + v);
            out[(size_t)row*128 + col] = v;
        }
    }
}

// ---------------------------------------------------------------------------
// scores + softmax over centroids -> g_nm.   64 nodes / block, 256 threads
// ---------------------------------------------------------------------------
__global__ void nm_kernel(const float* __restrict__ x,
                          const float* __restrict__ W_score) {
    __shared__ float xs[64*129];
    __shared__ float ss[64*8];
    __shared__ float Ws[128*8];
    int tid = threadIdx.x;
    int n0 = blockIdx.x * 64;

    for (int i = tid; i < 64*128; i += 256) {
        int rw = i >> 7, k = i & 127;
        xs[rw*129 + k] = x[(size_t)(n0 + rw)*128 + k];
    }
    for (int i = tid; i < 128*8; i += 256) Ws[i] = W_score[i];
    __syncthreads();

    int node = tid >> 2, q = tid & 3;
    float s0 = 0.f, s1 = 0.f;
    for (int k = 0; k < 128; k++) {
        float a = xs[node*129 + k];
        s0 = fmaf(a, Ws[k*8 + q], s0);
        s1 = fmaf(a, Ws[k*8 + q + 4], s1);
    }
    ss[node*8 + q]     = s0;
    ss[node*8 + q + 4] = s1;
    __syncthreads();

    if (tid < 128) {
        int nd = tid >> 1, r = tid & 1;
        float v[4];
#pragma unroll
        for (int c = 0; c < 4; c++) v[c] = ss[nd*8 + c*2 + r];
        float m = fmaxf(fmaxf(v[0], v[1]), fmaxf(v[2], v[3]));
        float e[4], sum = 0.f;
#pragma unroll
        for (int c = 0; c < 4; c++) { e[c] = expf(v[c] - m); sum += e[c]; }
        float inv = 1.f / sum;
        int n = n0 + nd;
#pragma unroll
        for (int c = 0; c < 4; c++)
            g_nm[(size_t)(r*4 + c)*NN + n] = e[c] * inv;
    }
}

// ---------------------------------------------------------------------------
// per-graph fused kernel: agg_bb (local CSR), num/denom -> cent_x, agg_bc,
// centroid-pair weights -> raw Wcc.  1 block / graph, 256 threads.
// ---------------------------------------------------------------------------
__global__ void graph_kernel(const float* __restrict__ x,
                             const float* __restrict__ h,
                             const float* __restrict__ eemb,
                             const int* __restrict__ ei) {
    extern __shared__ float smf[];
    float* nm_sm    = smf;                 // 8*256
    float* wnum     = nm_sm + 2048;        // 1024*8
    float* num_sm   = wnum + 8192;         // 8*128
    float* bc_sm    = num_sm + 1024;       // 8*128
    float* w_sm     = bc_sm + 1024;        // 24 (use 20)
    float* denom_sm = w_sm + 24;           // 8
    int* sl  = (int*)(denom_sm + 8);       // 1024
    int* dl  = sl + EPG;                   // 1024
    int* deg = dl + EPG;                   // 256
    int* off = deg + PN;                   // 257
    int* cur = off + PN + 1;               // 256
    int* csr = cur + PN;                   // 1024

    const int g = blockIdx.x;
    const int tid = threadIdx.x;
    const int gb = g * PN;
    const int ge = g * EPG;

    for (int i = tid; i < PN; i += 256) deg[i] = 0;
    if (tid < 20) w_sm[tid] = 0.f;
    for (int i = tid; i < 8*PN; i += 256)
        nm_sm[i] = g_nm[(size_t)(i >> 8)*NN + gb + (i & 255)];
    __syncthreads();

    float wp[20];
#pragma unroll
    for (int p = 0; p < 20; p++) wp[p] = 0.f;

    for (int e = tid; e < EPG; e += 256) {
        int s = ei[ge + e] - gb;
        int d = ei[NE + ge + e] - gb;
        sl[e] = s; dl[e] = d;
        atomicAdd(&deg[d], 1);
        float ns[8], nd[8];
#pragma unroll
        for (int rc = 0; rc < 8; rc++) {
            ns[rc] = nm_sm[rc*256 + s];
            nd[rc] = nm_sm[rc*256 + d];
            wnum[e*8 + rc] = nd[rc]*nd[rc]*ns[rc];
        }
#pragma unroll
        for (int r = 0; r < 2; r++) {
            int b = r*4, w0 = r*10;
            wp[w0+0] += ns[b+0]*nd[b+1];
            wp[w0+1] += ns[b+0]*nd[b+2];
            wp[w0+2] += ns[b+0]*nd[b+3];
            wp[w0+3] += ns[b+1]*nd[b+2];
            wp[w0+4] += ns[b+1]*nd[b+3];
            wp[w0+5] += ns[b+2]*nd[b+3];
#pragma unroll
            for (int c = 0; c < 4; c++) wp[w0+6+c] += ns[b+c]*nd[b+c];
        }
    }
#pragma unroll
    for (int p = 0; p < 20; p++)
        for (int o = 16; o > 0; o >>= 1)
            wp[p] += __shfl_down_sync(0xffffffffu, wp[p], o);
    if ((tid & 31) == 0)
#pragma unroll
        for (int p = 0; p < 20; p++) atomicAdd(&w_sm[p], wp[p]);
    __syncthreads();

    if (tid == 0) {
        int a = 0;
        for (int i = 0; i < PN; i++) { off[i] = a; a += deg[i]; }
        off[PN] = a;
    }
    __syncthreads();
    for (int i = tid; i < PN; i += 256) cur[i] = off[i];
    __syncthreads();
    for (int e = tid; e < EPG; e += 256) {
        int pos = atomicAdd(&cur[dl[e]], 1);
        csr[pos] = e;
    }
    __syncthreads();

    // ---- vector phase: thread = (d, half) ----
    const int d = tid & 127, half = tid >> 7;
    float numa[8], bca[8];
#pragma unroll
    for (int rc = 0; rc < 8; rc++) { numa[rc] = 0.f; bca[rc] = 0.f; }

    for (int nl = half; nl < PN; nl += 2) {
        float xv = x[(size_t)(gb + nl)*128 + d];
        float hv = h[(size_t)(gb + nl)*128 + d];
#pragma unroll
        for (int rc = 0; rc < 8; rc++) {
            float wv = nm_sm[rc*256 + nl];
            numa[rc] = fmaf(wv, hv, numa[rc]);
            bca[rc]  = fmaf(wv, xv, bca[rc]);
        }
    }
    for (int e = half; e < EPG; e += 2) {
        float hv = h[(size_t)(gb + sl[e])*128 + d];
        float ev = eemb[(size_t)(ge + e)*128 + d];
        float m = hv + ev;
        float4 w0 = *reinterpret_cast<float4*>(&wnum[e*8]);
        float4 w1 = *reinterpret_cast<float4*>(&wnum[e*8 + 4]);
        numa[0] = fmaf(w0.x, m, numa[0]);
        numa[1] = fmaf(w0.y, m, numa[1]);
        numa[2] = fmaf(w0.z, m, numa[2]);
        numa[3] = fmaf(w0.w, m, numa[3]);
        numa[4] = fmaf(w1.x, m, numa[4]);
        numa[5] = fmaf(w1.y, m, numa[5]);
        numa[6] = fmaf(w1.z, m, numa[6]);
        numa[7] = fmaf(w1.w, m, numa[7]);
    }
    // agg_bb via local CSR (no atomics)
    for (int nl = half; nl < PN; nl += 2) {
        float acc = 0.f;
        int e0 = off[nl], e1 = off[nl + 1];
        for (int ii = e0; ii < e1; ii++) {
            int e = csr[ii];
            acc += x[(size_t)(gb + sl[e])*128 + d]
                 + eemb[(size_t)(ge + e)*128 + d];
        }
        g_aggbb[(size_t)(gb + nl)*128 + d] = acc;
    }

    if (half == 0)
#pragma unroll
        for (int rc = 0; rc < 8; rc++) {
            num_sm[rc*128 + d] = numa[rc];
            bc_sm[rc*128 + d]  = bca[rc];
        }
    __syncthreads();
    if (half == 1)
#pragma unroll
        for (int rc = 0; rc < 8; rc++) {
            num_sm[rc*128 + d] += numa[rc];
            bc_sm[rc*128 + d]  += bca[rc];
        }
    __syncthreads();

    if (tid < 8) {
        float s = 0.f;
        for (int n = 0; n < PN; n++) s += nm_sm[tid*256 + n];
        denom_sm[tid] = s + 1e-6f;
    }
    __syncthreads();

    for (int i = tid; i < 8*128; i += 256) {
        int rc = i >> 7, dd = i & 127;
        int r = rc >> 2, c = rc & 3;
        size_t o = ((size_t)(r*NG + g)*4 + c)*128 + dd;
        g_centx[o] = num_sm[rc*128 + dd] / denom_sm[rc];
        g_aggbc[o] = bc_sm[rc*128 + dd];
    }

    if (tid < 32) {
        const int pidx[4][4] = { {6,0,1,2}, {0,7,3,4}, {1,3,8,5}, {2,4,5,9} };
        int r = tid >> 4, idx = tid & 15;
        int i = idx >> 2, j = idx & 3;
        float v = w_sm[r*10 + pidx[i][j]];
        if (i == j) v *= 0.5f;
        g_Wccraw[(r*NG + g)*16 + idx] = v;
    }
}

// ---------------------------------------------------------------------------
__global__ void maxred_kernel() {
    __shared__ float red[256];
    int tid = threadIdx.x;
    float m = 0.f;
    for (int i = tid; i < 2*NG*16; i += 256) m = fmaxf(m, g_Wccraw[i]);
    red[tid] = m; __syncthreads();
    for (int s = 128; s > 0; s >>= 1) {
        if (tid < s) red[tid] = fmaxf(red[tid], red[tid + s]);
        __syncthreads();
    }
    if (tid == 0) g_maxplus = red[0] + 1e-9f;
}

// ---------------------------------------------------------------------------
// h_cent = relu(agg_bc@W_bc + (Wcc_norm@cent_x)@W_cc + cent_x@W_sc)
// grid = 2*NG, 128 threads
// ---------------------------------------------------------------------------
__global__ void hcent_kernel(const float* __restrict__ Wbc,
                             const float* __restrict__ Wcc,
                             const float* __restrict__ Wsc) {
    __shared__ float cx[4*128], bc[4*128], cc[4*128], Wg[16];
    int b = blockIdx.x; int r = b / NG; int g = b % NG;
    int d = threadIdx.x;
    size_t base = (size_t)(r*NG + g) * 512;
    for (int i = d; i < 512; i += 128) {
        cx[i] = g_centx[base + i];
        bc[i] = g_aggbc[base + i];
    }
    if (d < 16) Wg[d] = g_Wccraw[(r*NG + g)*16 + d] / g_maxplus;
    __syncthreads();
#pragma unroll
    for (int i = 0; i < 4; i++) {
        float a = 0.f;
#pragma unroll
        for (int j = 0; j < 4; j++) a = fmaf(Wg[i*4 + j], cx[j*128 + d], a);
        cc[i*128 + d] = a;
    }
    __syncthreads();
    float acc[4] = {0.f, 0.f, 0.f, 0.f};
    for (int k = 0; k < 128; k++) {
        float wb = Wbc[k*128 + d], wc = Wcc[k*128 + d], ws = Wsc[k*128 + d];
#pragma unroll
        for (int c = 0; c < 4; c++) {
            acc[c] = fmaf(bc[c*128 + k], wb, acc[c]);
            acc[c] = fmaf(cc[c*128 + k], wc, acc[c]);
            acc[c] = fmaf(cx[c*128 + k], ws, acc[c]);
        }
    }
#pragma unroll
    for (int c = 0; c < 4; c++)
        g_hcent[base + c*128 + d] = fmaxf(acc[c], 0.f);
}

// ---------------------------------------------------------------------------
// agg_cb[r,n,d] = sum_c nm[r,c,n] * h_cent[r, g(n), c, d].  grid = NG
// ---------------------------------------------------------------------------
__global__ void aggcb_kernel() {
    __shared__ float hc[1024];
    __shared__ float nm_s[2048];
    int g = blockIdx.x, tid = threadIdx.x;
    for (int i = tid; i < 1024; i += 256) {
        int r = i >> 9, rest = i & 511;
        hc[i] = g_hcent[(size_t)(r*NG + g)*512 + rest];
    }
    for (int i = tid; i < 2048; i += 256)
        nm_s[i] = g_nm[(size_t)(i >> 8)*NN + g*PN + (i & 255)];
    __syncthreads();
    int d = tid & 127, half = tid >> 7;
    for (int nl = half; nl < PN; nl += 2) {
#pragma unroll
        for (int r = 0; r < 2; r++) {
            float a = 0.f;
#pragma unroll
            for (int c = 0; c < 4; c++)
                a = fmaf(nm_s[(r*4 + c)*256 + nl], hc[r*512 + c*128 + d], a);
            g_aggcb[(size_t)r*NN*128 + (size_t)(g*PN + nl)*128 + d] = a;
        }
    }
}

// ---------------------------------------------------------------------------
// graph pool + inter head + out head.  grid = NG, 128 threads
// ---------------------------------------------------------------------------
__global__ void poolhead_kernel(const float* __restrict__ W_inter,
                                const float* __restrict__ b_inter,
                                const float* __restrict__ W_out,
                                const float* __restrict__ b_out,
                                float* __restrict__ out) {
    __shared__ float gs[128], emb[128];
    int g = blockIdx.x, d = threadIdx.x;
    float s = 0.f;
    for (int n = 0; n < PN; n++) s += g_hbm[(size_t)(g*PN + n)*128 + d];
    gs[d] = s * (1.0f / PN);
    __syncthreads();
    float a = b_inter[d];
    for (int k = 0; k < 128; k++) a = fmaf(gs[k], W_inter[k*128 + d], a);
    emb[d] = a;
    __syncthreads();
    if (d < OUTD) {
        float o = b_out[d];
        for (int k = 0; k < 128; k++) o = fmaf(emb[k], W_out[k*OUTD + d], o);
        out[g*OUTD + d] = o;
    }
}

// ---------------------------------------------------------------------------
extern "C" void kernel_launch(void* const* d_in, const int* in_sizes, int n_in,
                              void* d_out, int out_size) {
    const float* x_feat    = (const float*)d_in[0];
    const float* edge_attr = (const float*)d_in[1];
    const float* W_atom    = (const float*)d_in[2];
    const float* b_atom    = (const float*)d_in[3];
    const float* W_score   = (const float*)d_in[4];
    const float* W_edge    = (const float*)d_in[5];
    const float* W_b2c     = (const float*)d_in[6];
    const float* W_bb      = (const float*)d_in[7];
    const float* W_bc      = (const float*)d_in[8];
    const float* W_cb      = (const float*)d_in[9];
    const float* W_cc      = (const float*)d_in[10];
    const float* W_sb      = (const float*)d_in[11];
    const float* W_sc      = (const float*)d_in[12];
    const float* W_inter   = (const float*)d_in[13];
    const float* b_inter   = (const float*)d_in[14];
    const float* W_out     = (const float*)d_in[15];
    const float* b_out     = (const float*)d_in[16];
    const int*   edge_index= (const int*)d_in[17];
    float* out = (float*)d_out;

    cudaFuncSetAttribute(gemm128, cudaFuncAttributeMaxDynamicSharedMemorySize, 139776);
    cudaFuncSetAttribute(graph_kernel, cudaFuncAttributeMaxDynamicSharedMemorySize, 64644);

    void *px_, *ph_, *pe_, *pbb_, *pcb_, *pZ_, *phbm_;
    cudaGetSymbolAddress(&px_,  g_x);
    cudaGetSymbolAddress(&ph_,  g_h);
    cudaGetSymbolAddress(&pe_,  g_eemb);
    cudaGetSymbolAddress(&pbb_, g_aggbb);
    cudaGetSymbolAddress(&pcb_, g_aggcb);
    cudaGetSymbolAddress(&pZ_,  g_Z);
    cudaGetSymbolAddress(&phbm_,g_hbm);
    float* px   = (float*)px_;
    float* ph   = (float*)ph_;
    float* pe   = (float*)pe_;
    float* pbb  = (float*)pbb_;
    float* pcb  = (float*)pcb_;
    float* pZ   = (float*)pZ_;
    float* phbm = (float*)phbm_;

    const size_t smA = 128*17*4;

    // 1. x = x_feat @ W_atom + b_atom
    gemm128<<<NN/128, 256, 64*128*4 + smA>>>(
        x_feat, W_atom, 64, nullptr, nullptr, b_atom, nullptr, nullptr, 0, px);
    // 2. nm (scores + softmax)
    nm_kernel<<<NN/64, 256>>>(px, W_score);
    // 3. edge embedding
    gemm128<<<NE/128, 256, 16*128*4 + smA>>>(
        edge_attr, W_edge, 16, nullptr, nullptr, nullptr, nullptr, nullptr, 0, pe);
    // 4. h = relu(x @ W_b2c)
    gemm128<<<NN/128, 256, 128*128*4 + smA>>>(
        px, W_b2c, 128, nullptr, nullptr, nullptr, nullptr, nullptr, 1, ph);
    // 5. fused per-graph pass
    graph_kernel<<<NG, 256, 64644>>>(px, ph, pe, edge_index);
    // 6. global max for Wcc normalization
    maxred_kernel<<<1, 256>>>();
    // 7. h_cent
    hcent_kernel<<<2*NG, 128>>>(W_bc, W_cc, W_sc);
    // 8. agg_cb
    aggcb_kernel<<<NG, 256>>>();
    // 9. Z = agg_bb@W_bb + x@W_sb
    gemm128<<<NN/128, 256, 2*128*128*4 + smA>>>(
        pbb, W_bb, 128, px, W_sb, nullptr, nullptr, nullptr, 0, pZ);
    // 10. h_base r=0: hbm = relu(Z + aggcb0@W_cb)
    gemm128<<<NN/128, 256, 128*128*4 + smA>>>(
        pcb, W_cb, 128, nullptr, nullptr, nullptr, pZ, nullptr, 1, phbm);
    // 11. h_base r=1 + mean:  hbm = 0.5*(hbm + relu(Z + aggcb1@W_cb))
    gemm128<<<NN/128, 256, 128*128*4 + smA>>>(
        pcb + (size_t)NN*128, W_cb, 128, nullptr, nullptr, nullptr, pZ, phbm, 1, phbm);
    // 12. pool + heads
    poolhead_kernel<<<NG, 128>>>(W_inter, b_inter, W_out, b_out, out);
}

// round 3
// speedup vs baseline: 1.8147x; 1.8147x over previous
#include <cuda_runtime.h>
#include <math.h>

#define NG   128
#define PN   256
#define EPG  1024
#define NN   (NG*PN)     // 32768
#define NE   (NG*EPG)    // 131072
#define DD   128
#define OUTD 10

// ---------------- device scratch (static, no runtime alloc) ----------------
__device__ float g_x[NN*DD];
__device__ float g_h[NN*DD];
__device__ float g_nm[8*NN];              // [(r*4+c)*NN + n]
__device__ float g_aggbb[NN*DD];          // x-part of agg_bb
__device__ float g_aggea[NN*16];          // edge_attr scatter
__device__ float g_numh[2*NG*4*DD];       // num (h-part, un-divided)
__device__ float g_aggbc[2*NG*4*DD];
__device__ float g_den[2*NG*4];
__device__ float g_numea[2*NG*4*16];
__device__ float g_Wccraw[2*NG*16];
__device__ float g_maxplus;
__device__ float g_hcw[2*NG*4*DD];        // h_cent @ W_cb
__device__ float g_Z[NN*DD];
__device__ float g_W3[16*DD];             // W_edge @ W_bb

// ---------------- packed f32x2 helpers ----------------
typedef unsigned long long u64t;
__device__ __forceinline__ u64t pk2(float lo, float hi) {
    u64t r; asm("mov.b64 %0, {%1,%2};" : "=l"(r) : "f"(lo), "f"(hi)); return r;
}
__device__ __forceinline__ void upk2(u64t v, float& lo, float& hi) {
    asm("mov.b64 {%0,%1}, %2;" : "=f"(lo), "=f"(hi) : "l"(v));
}
__device__ __forceinline__ void fma2(u64t& d, u64t a, u64t b) {
    asm("fma.rn.f32x2 %0, %1, %2, %0;" : "+l"(d) : "l"(a), "l"(b));
}

// ---------------------------------------------------------------------------
// 128-col fp32 GEMM with packed f32x2 FMA.
// out = epi( A1@W1 [+ A2@W2] [+ A3@W3] )
// block: 128 rows x 128 cols, 256 threads; per-thread 8 rows x 4 col-pairs.
// ---------------------------------------------------------------------------
__device__ __forceinline__ void mma_pass2(const float* __restrict__ A, int K,
                                          const float* __restrict__ Ws,
                                          float* As, int row0, int tid,
                                          int tr, int tc2, u64t acc[8][4]) {
    float4 pre[2];
#pragma unroll
    for (int it = 0; it < 2; it++) {
        int idx = tid + it*256; int lr = idx >> 2, lc = (idx & 3) * 4;
        pre[it] = *(const float4*)(A + (size_t)(row0 + lr)*K + lc);
    }
    for (int k0 = 0; k0 < K; k0 += 16) {
        __syncthreads();
#pragma unroll
        for (int it = 0; it < 2; it++) {
            int idx = tid + it*256; int lr = idx >> 2, lc = (idx & 3) * 4;
            float4 v = pre[it];
            As[lr*17 + lc + 0] = v.x; As[lr*17 + lc + 1] = v.y;
            As[lr*17 + lc + 2] = v.z; As[lr*17 + lc + 3] = v.w;
        }
        __syncthreads();
        if (k0 + 16 < K) {
#pragma unroll
            for (int it = 0; it < 2; it++) {
                int idx = tid + it*256; int lr = idx >> 2, lc = (idx & 3) * 4;
                pre[it] = *(const float4*)(A + (size_t)(row0 + lr)*K + k0 + 16 + lc);
            }
        }
#pragma unroll
        for (int kk = 0; kk < 16; kk++) {
            const float* wrow = Ws + (k0 + kk)*128;
            u64t wv[4];
#pragma unroll
            for (int jp = 0; jp < 4; jp++)
                wv[jp] = *(const u64t*)(wrow + tc2 + 32*jp);
#pragma unroll
            for (int i = 0; i < 8; i++) {
                float a = As[(tr + 16*i)*17 + kk];
                u64t ap = pk2(a, a);
#pragma unroll
                for (int jp = 0; jp < 4; jp++) fma2(acc[i][jp], ap, wv[jp]);
            }
        }
    }
}

__global__ void gemm128(const float* __restrict__ A1, const float* __restrict__ W1, int K1,
                        const float* __restrict__ A2, const float* __restrict__ W2, int K2,
                        const float* __restrict__ A3, const float* __restrict__ W3, int K3,
                        const float* __restrict__ bias, int relu_flag,
                        float* __restrict__ out) {
    extern __shared__ float sm[];
    float* Ws1 = sm;
    float* Ws2 = Ws1 + K1*128;
    float* Ws3 = Ws2 + K2*128;
    float* As  = Ws3 + K3*128;

    const int tid = threadIdx.x;
    const int tr = tid >> 4, tc2 = (tid & 15) * 2;
    const int row0 = blockIdx.x * 128;

    for (int i = tid*4; i < K1*128; i += 1024) *(float4*)(Ws1+i) = *(const float4*)(W1+i);
    if (A2) for (int i = tid*4; i < K2*128; i += 1024) *(float4*)(Ws2+i) = *(const float4*)(W2+i);
    if (A3) for (int i = tid*4; i < K3*128; i += 1024) *(float4*)(Ws3+i) = *(const float4*)(W3+i);

    u64t acc[8][4];
#pragma unroll
    for (int i = 0; i < 8; i++)
#pragma unroll
        for (int j = 0; j < 4; j++) acc[i][j] = 0ull;

    mma_pass2(A1, K1, Ws1, As, row0, tid, tr, tc2, acc);
    if (A2) mma_pass2(A2, K2, Ws2, As, row0, tid, tr, tc2, acc);
    if (A3) mma_pass2(A3, K3, Ws3, As, row0, tid, tr, tc2, acc);

#pragma unroll
    for (int i = 0; i < 8; i++) {
        int row = row0 + tr + 16*i;
#pragma unroll
        for (int jp = 0; jp < 4; jp++) {
            int cb = tc2 + 32*jp;
            float lo, hi; upk2(acc[i][jp], lo, hi);
            if (bias) { lo += bias[cb]; hi += bias[cb+1]; }
            if (relu_flag) { lo = fmaxf(lo, 0.f); hi = fmaxf(hi, 0.f); }
            out[(size_t)row*128 + cb]     = lo;
            out[(size_t)row*128 + cb + 1] = hi;
        }
    }
}

// ---------------------------------------------------------------------------
// scores + softmax -> g_nm.  64 nodes / block, 256 threads
// ---------------------------------------------------------------------------
__global__ void nm_kernel(const float* __restrict__ x,
                          const float* __restrict__ W_score) {
    __shared__ float xs[64*129];
    __shared__ float ss[64*8];
    __shared__ float Ws[128*8];
    int tid = threadIdx.x;
    int n0 = blockIdx.x * 64;

    for (int i = tid; i < 64*128; i += 256) {
        int rw = i >> 7, k = i & 127;
        xs[rw*129 + k] = x[(size_t)(n0 + rw)*128 + k];
    }
    for (int i = tid; i < 128*8; i += 256) Ws[i] = W_score[i];
    __syncthreads();

    int node = tid >> 2, q = tid & 3;
    float s0 = 0.f, s1 = 0.f;
    for (int k = 0; k < 128; k++) {
        float a = xs[node*129 + k];
        s0 = fmaf(a, Ws[k*8 + q], s0);
        s1 = fmaf(a, Ws[k*8 + q + 4], s1);
    }
    ss[node*8 + q]     = s0;
    ss[node*8 + q + 4] = s1;
    __syncthreads();

    if (tid < 128) {
        int nd = tid >> 1, r = tid & 1;
        float v[4];
#pragma unroll
        for (int c = 0; c < 4; c++) v[c] = ss[nd*8 + c*2 + r];
        float m = fmaxf(fmaxf(v[0], v[1]), fmaxf(v[2], v[3]));
        float e[4], sum = 0.f;
#pragma unroll
        for (int c = 0; c < 4; c++) { e[c] = expf(v[c] - m); sum += e[c]; }
        float inv = 1.f / sum;
        int n = n0 + nd;
#pragma unroll
        for (int c = 0; c < 4; c++)
            g_nm[(size_t)(r*4 + c)*NN + n] = e[c] * inv;
    }
}

// ---------------------------------------------------------------------------
// W3 = W_edge @ W_bb   [16,128]@[128,128]
// ---------------------------------------------------------------------------
__global__ void prep_kernel(const float* __restrict__ Wedge,
                            const float* __restrict__ Wbb) {
    __shared__ float We[16*128];
    int tid = threadIdx.x;
    for (int i = tid; i < 2048; i += 256) We[i] = Wedge[i];
    __syncthreads();
    for (int o = tid; o < 2048; o += 256) {
        int q = o >> 7, d = o & 127;
        float a = 0.f;
        for (int k = 0; k < 128; k++) a = fmaf(We[q*128 + k], Wbb[k*128 + d], a);
        g_W3[o] = a;
    }
}

// ---------------------------------------------------------------------------
// Per-graph fused kernel.  1 block / graph, 256 threads.
// Outputs: g_aggbb (x-part CSR), g_aggea, g_numh, g_den, g_aggbc, g_numea,
//          g_Wccraw.
// ---------------------------------------------------------------------------
__global__ void graph_kernel(const float* __restrict__ x,
                             const float* __restrict__ h,
                             const float* __restrict__ edge_attr,
                             const int* __restrict__ ei) {
    extern __shared__ float smf[];
    float* nm_sm   = smf;             // 2048
    float* srcw    = nm_sm + 2048;    // 2048
    float* ea_sm   = srcw + 2048;     // 4096  (chunk: 256 edges x 16)
    float* wnum_c  = ea_sm + 4096;    // 2048  (chunk: 256 x 8)
    float* numh_sm = wnum_c + 2048;   // 1024
    float* bc_sm   = numh_sm + 1024;  // 1024
    float* red_sm  = bc_sm + 1024;    // 256
    float* w_sm    = red_sm + 256;    // 24
    float* den_sm  = w_sm + 24;       // 8
    int* sl  = (int*)(den_sm + 8);    // 1024
    int* dl  = sl + 1024;             // 1024
    int* deg = dl + 1024;             // 256
    int* off = deg + 256;             // 257
    int* cur = off + 257;             // 256
    int* csr = cur + 256;             // 1024

    const int g = blockIdx.x;
    const int tid = threadIdx.x;
    const int gb = g * PN;
    const int ge = g * EPG;

    for (int i = tid; i < PN; i += 256) deg[i] = 0;
    if (tid < 20) w_sm[tid] = 0.f;
    for (int i = tid; i < 2048; i += 256) {
        srcw[i] = 0.f;
        nm_sm[i] = g_nm[(size_t)(i >> 8)*NN + gb + (i & 255)];
    }
    __syncthreads();

    float wp[20];
#pragma unroll
    for (int p = 0; p < 20; p++) wp[p] = 0.f;
    float nacc = 0.f;
    const int eh = tid >> 7, rcb = (tid >> 4) & 7, qb = tid & 15;

    for (int c0 = 0; c0 < EPG; c0 += 256) {
        int e = c0 + tid;
        int s = ei[ge + e] - gb;
        int d = ei[NE + ge + e] - gb;
        sl[e] = s; dl[e] = d;
        atomicAdd(&deg[d], 1);
        const float4* earow = (const float4*)(edge_attr + (size_t)(ge + e)*16);
        float4* eadst = (float4*)(ea_sm + tid*16);
        eadst[0] = earow[0]; eadst[1] = earow[1];
        eadst[2] = earow[2]; eadst[3] = earow[3];

        float ns[8], nd[8];
#pragma unroll
        for (int rc = 0; rc < 8; rc++) {
            ns[rc] = nm_sm[rc*256 + s];
            nd[rc] = nm_sm[rc*256 + d];
            float wv = nd[rc]*nd[rc]*ns[rc];
            wnum_c[tid*8 + rc] = wv;
            atomicAdd(&srcw[rc*256 + s], wv);
        }
#pragma unroll
        for (int r = 0; r < 2; r++) {
            int b = r*4, w0 = r*10;
            wp[w0+0] += ns[b+0]*nd[b+1];
            wp[w0+1] += ns[b+0]*nd[b+2];
            wp[w0+2] += ns[b+0]*nd[b+3];
            wp[w0+3] += ns[b+1]*nd[b+2];
            wp[w0+4] += ns[b+1]*nd[b+3];
            wp[w0+5] += ns[b+2]*nd[b+3];
#pragma unroll
            for (int c = 0; c < 4; c++) wp[w0+6+c] += ns[b+c]*nd[b+c];
        }
        __syncthreads();
        // numea partial: thread = (eh, rc, q)
        for (int el = eh*128; el < eh*128 + 128; el++)
            nacc = fmaf(wnum_c[el*8 + rcb], ea_sm[el*16 + qb], nacc);
        __syncthreads();
    }

    // reduce numea over eh halves
    red_sm[tid] = nacc;
    __syncthreads();
    if (tid < 128) {
        float v = red_sm[tid] + red_sm[tid + 128];
        int rc = tid >> 4, q = tid & 15;
        int r = rc >> 2, c = rc & 3;
        g_numea[((size_t)(r*NG + g)*4 + c)*16 + q] = v;
    }

    // pair-weight reduce
#pragma unroll
    for (int p = 0; p < 20; p++)
        for (int o = 16; o > 0; o >>= 1)
            wp[p] += __shfl_down_sync(0xffffffffu, wp[p], o);
    if ((tid & 31) == 0)
#pragma unroll
        for (int p = 0; p < 20; p++) atomicAdd(&w_sm[p], wp[p]);
    __syncthreads();

    // CSR build
    if (tid == 0) {
        int a = 0;
        for (int i = 0; i < PN; i++) { off[i] = a; a += deg[i]; }
        off[PN] = a;
    }
    __syncthreads();
    for (int i = tid; i < PN; i += 256) cur[i] = off[i];
    __syncthreads();
    for (int e = tid; e < EPG; e += 256) {
        int pos = atomicAdd(&cur[dl[e]], 1);
        csr[pos] = e;
    }
    __syncthreads();

    // aggea via CSR: thread = (node, q)
    for (int i = tid; i < PN*16; i += 256) {
        int nl = i >> 4, q = i & 15;
        float a = 0.f;
        int e0 = off[nl], e1 = off[nl + 1];
        for (int ii = e0; ii < e1; ii++)
            a += edge_attr[(size_t)(ge + csr[ii])*16 + q];
        g_aggea[(size_t)(gb + nl)*16 + q] = a;
    }

    // ---- vector phase: thread = (d, half) ----
    const int d = tid & 127, half = tid >> 7;
    float numa[8], bca[8];
#pragma unroll
    for (int rc = 0; rc < 8; rc++) { numa[rc] = 0.f; bca[rc] = 0.f; }

    for (int nl = half; nl < PN; nl += 2) {
        float xv = x[(size_t)(gb + nl)*128 + d];
        float hv = h[(size_t)(gb + nl)*128 + d];
#pragma unroll
        for (int rc = 0; rc < 8; rc++) {
            float w1 = nm_sm[rc*256 + nl];
            numa[rc] = fmaf(w1 + srcw[rc*256 + nl], hv, numa[rc]);
            bca[rc]  = fmaf(w1, xv, bca[rc]);
        }
    }
    // agg_bb (x part) via CSR
    for (int nl = half; nl < PN; nl += 2) {
        float acc = 0.f;
        int e0 = off[nl], e1 = off[nl + 1];
        for (int ii = e0; ii < e1; ii++)
            acc += x[(size_t)(gb + sl[csr[ii]])*128 + d];
        g_aggbb[(size_t)(gb + nl)*128 + d] = acc;
    }

    if (half == 0)
#pragma unroll
        for (int rc = 0; rc < 8; rc++) {
            numh_sm[rc*128 + d] = numa[rc];
            bc_sm[rc*128 + d]   = bca[rc];
        }
    __syncthreads();
    if (half == 1)
#pragma unroll
        for (int rc = 0; rc < 8; rc++) {
            numh_sm[rc*128 + d] += numa[rc];
            bc_sm[rc*128 + d]   += bca[rc];
        }
    __syncthreads();

    if (tid < 8) {
        float s = 0.f;
        for (int n = 0; n < PN; n++) s += nm_sm[tid*256 + n];
        den_sm[tid] = s + 1e-6f;
    }
    __syncthreads();

    for (int i = tid; i < 8*128; i += 256) {
        int rc = i >> 7, dd = i & 127;
        int r = rc >> 2, c = rc & 3;
        size_t o = ((size_t)(r*NG + g)*4 + c)*128 + dd;
        g_numh[o]  = numh_sm[rc*128 + dd];
        g_aggbc[o] = bc_sm[rc*128 + dd];
    }
    if (tid < 8) {
        int r = tid >> 2, c = tid & 3;
        g_den[(size_t)(r*NG + g)*4 + c] = den_sm[tid];
    }

    if (tid < 32) {
        const int pidx[4][4] = { {6,0,1,2}, {0,7,3,4}, {1,3,8,5}, {2,4,5,9} };
        int r = tid >> 4, idx = tid & 15;
        int i = idx >> 2, j = idx & 3;
        float v = w_sm[r*10 + pidx[i][j]];
        if (i == j) v *= 0.5f;
        g_Wccraw[(r*NG + g)*16 + idx] = v;
    }
}

// ---------------------------------------------------------------------------
__global__ void maxred_kernel() {
    __shared__ float red[256];
    int tid = threadIdx.x;
    float m = 0.f;
    for (int i = tid; i < 2*NG*16; i += 256) m = fmaxf(m, g_Wccraw[i]);
    red[tid] = m; __syncthreads();
    for (int s = 128; s > 0; s >>= 1) {
        if (tid < s) red[tid] = fmaxf(red[tid], red[tid + s]);
        __syncthreads();
    }
    if (tid == 0) g_maxplus = red[0] + 1e-9f;
}

// ---------------------------------------------------------------------------
// per (r,g): cent_x = (numh + numea@W_edge)/den;  cc = Wg@cent_x;
// h_cent = relu(bc@Wbc + cc@Wcc + cx@Wsc);  hcw = h_cent@Wcb
// grid = 2*NG, 128 threads
// ---------------------------------------------------------------------------
__global__ void hcent_kernel(const float* __restrict__ Wedge,
                             const float* __restrict__ Wbc,
                             const float* __restrict__ Wcc_,
                             const float* __restrict__ Wsc,
                             const float* __restrict__ Wcb) {
    __shared__ float We[16*128], cx[512], bc[512], cc[512], hc[512];
    __shared__ float numea[64], Wg[16], den[4];
    int b = blockIdx.x;                 // b = r*NG + g
    int d = threadIdx.x;
    size_t base = (size_t)b * 512;

    for (int i = d; i < 2048; i += 128) We[i] = Wedge[i];
    for (int i = d; i < 512; i += 128) {
        cx[i] = g_numh[base + i];
        bc[i] = g_aggbc[base + i];
    }
    if (d < 64) numea[d] = g_numea[(size_t)b*64 + d];
    if (d < 16) Wg[d] = g_Wccraw[b*16 + d] / g_maxplus;
    if (d < 4)  den[d] = g_den[(size_t)b*4 + d];
    __syncthreads();

#pragma unroll
    for (int c = 0; c < 4; c++) {
        float v = cx[c*128 + d];
#pragma unroll
        for (int q = 0; q < 16; q++)
            v = fmaf(numea[c*16 + q], We[q*128 + d], v);
        cx[c*128 + d] = v / den[c];
    }
    __syncthreads();
#pragma unroll
    for (int c = 0; c < 4; c++) {
        float a = 0.f;
#pragma unroll
        for (int j = 0; j < 4; j++) a = fmaf(Wg[c*4 + j], cx[j*128 + d], a);
        cc[c*128 + d] = a;
    }
    __syncthreads();
    float acc[4] = {0.f, 0.f, 0.f, 0.f};
    for (int k = 0; k < 128; k++) {
        float wb = Wbc[k*128 + d], wc = Wcc_[k*128 + d], ws = Wsc[k*128 + d];
#pragma unroll
        for (int c = 0; c < 4; c++) {
            acc[c] = fmaf(bc[c*128 + k], wb, acc[c]);
            acc[c] = fmaf(cc[c*128 + k], wc, acc[c]);
            acc[c] = fmaf(cx[c*128 + k], ws, acc[c]);
        }
    }
#pragma unroll
    for (int c = 0; c < 4; c++) hc[c*128 + d] = fmaxf(acc[c], 0.f);
    __syncthreads();
    float o[4] = {0.f, 0.f, 0.f, 0.f};
    for (int k = 0; k < 128; k++) {
        float w = Wcb[k*128 + d];
#pragma unroll
        for (int c = 0; c < 4; c++) o[c] = fmaf(hc[c*128 + k], w, o[c]);
    }
#pragma unroll
    for (int c = 0; c < 4; c++) g_hcw[base + c*128 + d] = o[c];
}

// ---------------------------------------------------------------------------
// Final fused: Y_r = Sum_c nm*hcw; node = mean_r relu(Z+Y_r);
// graph pool; inter head; out head.  grid = NG, 256 threads.
// ---------------------------------------------------------------------------
__global__ void final_kernel(const float* __restrict__ W_inter,
                             const float* __restrict__ b_inter,
                             const float* __restrict__ W_out,
                             const float* __restrict__ b_out,
                             float* __restrict__ out) {
    __shared__ float hcw[1024], nm_s[2048], red[256], gs[128], emb[128];
    int g = blockIdx.x, tid = threadIdx.x;
    for (int i = tid; i < 1024; i += 256) {
        int r = i >> 9;
        hcw[i] = g_hcw[(size_t)(r*NG + g)*512 + (i & 511)];
    }
    for (int i = tid; i < 2048; i += 256)
        nm_s[i] = g_nm[(size_t)(i >> 8)*NN + g*PN + (i & 255)];
    __syncthreads();

    int d = tid & 127, half = tid >> 7;
    float acc = 0.f;
    for (int nl = half; nl < PN; nl += 2) {
        float z = g_Z[(size_t)(g*PN + nl)*128 + d];
        float y0 = 0.f, y1 = 0.f;
#pragma unroll
        for (int c = 0; c < 4; c++) {
            y0 = fmaf(nm_s[c*256 + nl],       hcw[c*128 + d],       y0);
            y1 = fmaf(nm_s[(4 + c)*256 + nl], hcw[512 + c*128 + d], y1);
        }
        acc += 0.5f * (fmaxf(z + y0, 0.f) + fmaxf(z + y1, 0.f));
    }
    red[tid] = acc;
    __syncthreads();
    if (tid < 128) gs[tid] = (red[tid] + red[tid + 128]) * (1.0f / PN);
    __syncthreads();
    if (tid < 128) {
        float e = b_inter[tid];
        for (int k = 0; k < 128; k++) e = fmaf(gs[k], W_inter[k*128 + tid], e);
        emb[tid] = e;
    }
    __syncthreads();
    if (tid < OUTD) {
        float o = b_out[tid];
        for (int k = 0; k < 128; k++) o = fmaf(emb[k], W_out[k*OUTD + tid], o);
        out[g*OUTD + tid] = o;
    }
}

// ---------------------------------------------------------------------------
extern "C" void kernel_launch(void* const* d_in, const int* in_sizes, int n_in,
                              void* d_out, int out_size) {
    const float* x_feat    = (const float*)d_in[0];
    const float* edge_attr = (const float*)d_in[1];
    const float* W_atom    = (const float*)d_in[2];
    const float* b_atom    = (const float*)d_in[3];
    const float* W_score   = (const float*)d_in[4];
    const float* W_edge    = (const float*)d_in[5];
    const float* W_b2c     = (const float*)d_in[6];
    const float* W_bb      = (const float*)d_in[7];
    const float* W_bc      = (const float*)d_in[8];
    const float* W_cb      = (const float*)d_in[9];
    const float* W_cc      = (const float*)d_in[10];
    const float* W_sb      = (const float*)d_in[11];
    const float* W_sc      = (const float*)d_in[12];
    const float* W_inter   = (const float*)d_in[13];
    const float* b_inter   = (const float*)d_in[14];
    const float* W_out     = (const float*)d_in[15];
    const float* b_out     = (const float*)d_in[16];
    const int*   edge_index= (const int*)d_in[17];
    float* out = (float*)d_out;

    cudaFuncSetAttribute(gemm128, cudaFuncAttributeMaxDynamicSharedMemorySize, 150000);
    cudaFuncSetAttribute(graph_kernel, cudaFuncAttributeMaxDynamicSharedMemorySize, 66000);

    void *px_, *ph_, *pbb_, *pea_, *pZ_, *pW3_;
    cudaGetSymbolAddress(&px_,  g_x);
    cudaGetSymbolAddress(&ph_,  g_h);
    cudaGetSymbolAddress(&pbb_, g_aggbb);
    cudaGetSymbolAddress(&pea_, g_aggea);
    cudaGetSymbolAddress(&pZ_,  g_Z);
    cudaGetSymbolAddress(&pW3_, g_W3);
    float* px  = (float*)px_;
    float* ph  = (float*)ph_;
    float* pbb = (float*)pbb_;
    float* pea = (float*)pea_;
    float* pZ  = (float*)pZ_;
    float* pW3 = (float*)pW3_;

    const size_t smA = 128*17*4;   // 8704

    // 1. x = x_feat @ W_atom + b_atom          (K=64)
    gemm128<<<NN/128, 256, 64*512 + smA>>>(
        x_feat, W_atom, 64, nullptr, nullptr, 0, nullptr, nullptr, 0,
        b_atom, 0, px);
    // 2. nm
    nm_kernel<<<NN/64, 256>>>(px, W_score);
    // 3. h = relu(x @ W_b2c)                   (K=128)
    gemm128<<<NN/128, 256, 128*512 + smA>>>(
        px, W_b2c, 128, nullptr, nullptr, 0, nullptr, nullptr, 0,
        nullptr, 1, ph);
    // 4. W3 = W_edge @ W_bb
    prep_kernel<<<1, 256>>>(W_edge, W_bb);
    // 5. per-graph fused pass
    graph_kernel<<<NG, 256, 65668>>>(px, ph, edge_attr, edge_index);
    // 6. max for Wcc normalization
    maxred_kernel<<<1, 256>>>();
    // 7. h_cent + hcw
    hcent_kernel<<<2*NG, 128>>>(W_edge, W_bc, W_cc, W_sc, W_cb);
    // 8. Z = aggbb@W_bb + x@W_sb + aggea@W3    (K=128+128+16)
    gemm128<<<NN/128, 256, (128+128+16)*512 + smA>>>(
        pbb, W_bb, 128, px, W_sb, 128, pea, pW3, 16,
        nullptr, 0, pZ);
    // 9. fused Y + relu + mean + pool + heads
    final_kernel<<<NG, 256>>>(W_inter, b_inter, W_out, b_out, out);
}

// round 4
// speedup vs baseline: 2.2773x; 1.2549x over previous
#include <cuda_runtime.h>
#include <math.h>

#define NG   128
#define PN   256
#define EPG  1024
#define NN   (NG*PN)     // 32768
#define NE   (NG*EPG)    // 131072
#define DD   128
#define OUTD 10

// ---------------- device scratch ----------------
__device__ float g_x[NN*DD];
__device__ float g_h[NN*DD];
__device__ float g_nm[8*NN];              // [(r*4+c)*NN + n]
__device__ float g_aggxf[NN*64];          // CSR-gathered x_feat
__device__ float g_deg[NN];
__device__ float g_aggea[NN*16];          // edge_attr scatter
__device__ float g_numh[2*NG*4*DD];
__device__ float g_aggbc[2*NG*4*DD];
__device__ float g_den[2*NG*4];
__device__ float g_numea[2*NG*4*16];
__device__ float g_Wccraw[2*NG*16];
__device__ float g_maxplus;
__device__ float g_hcw[2*NG*4*DD];
__device__ float g_Z[NN*DD];
// fused weights
__device__ float g_Wab[64*128];           // Wa@W_b2c
__device__ float g_Wasb[64*128];          // Wa@W_sb
__device__ float g_Wawbb[64*128];         // Wa@W_bb
__device__ float g_W3[16*128];            // We@W_bb
__device__ float g_biash[128];            // ba@W_b2c
__device__ float g_biasz[128];            // ba@W_sb
__device__ float g_babb[128];             // ba@W_bb
__device__ float g_Was[64*8];             // Wa@W_score
__device__ float g_bs[8];                 // ba@W_score

// ---------------- packed f32x2 helpers ----------------
typedef unsigned long long u64t;
__device__ __forceinline__ u64t pk2(float lo, float hi) {
    u64t r; asm("mov.b64 %0, {%1,%2};" : "=l"(r) : "f"(lo), "f"(hi)); return r;
}
__device__ __forceinline__ void upk2(u64t v, float& lo, float& hi) {
    asm("mov.b64 {%0,%1}, %2;" : "=f"(lo), "=f"(hi) : "l"(v));
}
__device__ __forceinline__ void fma2(u64t& d, u64t a, u64t b) {
    asm("fma.rn.f32x2 %0, %1, %2, %0;" : "+l"(d) : "l"(a), "l"(b));
}

// ---------------------------------------------------------------------------
// 128-col fp32 GEMM, packed f32x2 FMA, A staged pre-packed {a,a} in shared.
// out = epi( A1@W1 [+ A2@W2] [+ A3@W3] + bias + rowscale*rowvec )
// ---------------------------------------------------------------------------
__device__ __forceinline__ void mma_pass2(const float* __restrict__ A, int K,
                                          const float* __restrict__ Ws,
                                          u64t* As, int row0, int tid,
                                          int tr, int tc2, u64t acc[8][4]) {
    float4 pre[2];
#pragma unroll
    for (int it = 0; it < 2; it++) {
        int idx = tid + it*256; int lr = idx >> 2, lc = (idx & 3) * 4;
        pre[it] = *(const float4*)(A + (size_t)(row0 + lr)*K + lc);
    }
    for (int k0 = 0; k0 < K; k0 += 16) {
        __syncthreads();
#pragma unroll
        for (int it = 0; it < 2; it++) {
            int idx = tid + it*256; int lr = idx >> 2, lc = (idx & 3) * 4;
            float4 v = pre[it];
            As[lr*17 + lc + 0] = pk2(v.x, v.x);
            As[lr*17 + lc + 1] = pk2(v.y, v.y);
            As[lr*17 + lc + 2] = pk2(v.z, v.z);
            As[lr*17 + lc + 3] = pk2(v.w, v.w);
        }
        __syncthreads();
        if (k0 + 16 < K) {
#pragma unroll
            for (int it = 0; it < 2; it++) {
                int idx = tid + it*256; int lr = idx >> 2, lc = (idx & 3) * 4;
                pre[it] = *(const float4*)(A + (size_t)(row0 + lr)*K + k0 + 16 + lc);
            }
        }
#pragma unroll
        for (int kk = 0; kk < 16; kk++) {
            const float* wrow = Ws + (k0 + kk)*128;
            u64t wv[4];
#pragma unroll
            for (int jp = 0; jp < 4; jp++)
                wv[jp] = *(const u64t*)(wrow + tc2 + 32*jp);
#pragma unroll
            for (int i = 0; i < 8; i++) {
                u64t ap = As[(tr + 16*i)*17 + kk];
#pragma unroll
                for (int jp = 0; jp < 4; jp++) fma2(acc[i][jp], ap, wv[jp]);
            }
        }
    }
}

__global__ void gemm128(const float* __restrict__ A1, const float* __restrict__ W1, int K1,
                        const float* __restrict__ A2, const float* __restrict__ W2, int K2,
                        const float* __restrict__ A3, const float* __restrict__ W3, int K3,
                        const float* __restrict__ bias,
                        const float* __restrict__ rowscale,
                        const float* __restrict__ rowvec,
                        int relu_flag,
                        float* __restrict__ out) {
    extern __shared__ float sm[];
    float* Ws1 = sm;
    float* Ws2 = Ws1 + K1*128;
    float* Ws3 = Ws2 + K2*128;
    u64t*  As  = (u64t*)(Ws3 + K3*128);

    const int tid = threadIdx.x;
    const int tr = tid >> 4, tc2 = (tid & 15) * 2;
    const int row0 = blockIdx.x * 128;

    for (int i = tid*4; i < K1*128; i += 1024) *(float4*)(Ws1+i) = *(const float4*)(W1+i);
    if (A2) for (int i = tid*4; i < K2*128; i += 1024) *(float4*)(Ws2+i) = *(const float4*)(W2+i);
    if (A3) for (int i = tid*4; i < K3*128; i += 1024) *(float4*)(Ws3+i) = *(const float4*)(W3+i);

    u64t acc[8][4];
#pragma unroll
    for (int i = 0; i < 8; i++)
#pragma unroll
        for (int j = 0; j < 4; j++) acc[i][j] = 0ull;

    mma_pass2(A1, K1, Ws1, As, row0, tid, tr, tc2, acc);
    if (A2) mma_pass2(A2, K2, Ws2, As, row0, tid, tr, tc2, acc);
    if (A3) mma_pass2(A3, K3, Ws3, As, row0, tid, tr, tc2, acc);

#pragma unroll
    for (int i = 0; i < 8; i++) {
        int row = row0 + tr + 16*i;
        float rs = rowscale ? rowscale[row] : 0.f;
#pragma unroll
        for (int jp = 0; jp < 4; jp++) {
            int cb = tc2 + 32*jp;
            float lo, hi; upk2(acc[i][jp], lo, hi);
            if (bias)   { lo += bias[cb];        hi += bias[cb+1]; }
            if (rowvec) { lo += rs * rowvec[cb]; hi += rs * rowvec[cb+1]; }
            if (relu_flag) { lo = fmaxf(lo, 0.f); hi = fmaxf(hi, 0.f); }
            out[(size_t)row*128 + cb]     = lo;
            out[(size_t)row*128 + cb + 1] = hi;
        }
    }
}

// ---------------------------------------------------------------------------
// Parallel weight precompute.  grid = 212 blocks x 128 threads.
// ---------------------------------------------------------------------------
__global__ void prep_big(const float* __restrict__ Wa, const float* __restrict__ ba,
                         const float* __restrict__ Wb2c, const float* __restrict__ Wsb,
                         const float* __restrict__ Wbb, const float* __restrict__ We,
                         const float* __restrict__ Wscore) {
    int b = blockIdx.x, d = threadIdx.x;
    if (b < 64) {
        float a = 0.f;
        for (int k = 0; k < 128; k++) a = fmaf(Wa[b*128+k], Wb2c[k*128+d], a);
        g_Wab[b*128+d] = a;
    } else if (b < 128) {
        int f = b - 64; float a = 0.f;
        for (int k = 0; k < 128; k++) a = fmaf(Wa[f*128+k], Wsb[k*128+d], a);
        g_Wasb[f*128+d] = a;
    } else if (b < 144) {
        int q = b - 128; float a = 0.f;
        for (int k = 0; k < 128; k++) a = fmaf(We[q*128+k], Wbb[k*128+d], a);
        g_W3[q*128+d] = a;
    } else if (b < 208) {
        int f = b - 144; float a = 0.f;
        for (int k = 0; k < 128; k++) a = fmaf(Wa[f*128+k], Wbb[k*128+d], a);
        g_Wawbb[f*128+d] = a;
    } else if (b == 208) {
        float a = 0.f;
        for (int k = 0; k < 128; k++) a = fmaf(ba[k], Wb2c[k*128+d], a);
        g_biash[d] = a;
    } else if (b == 209) {
        float a = 0.f;
        for (int k = 0; k < 128; k++) a = fmaf(ba[k], Wsb[k*128+d], a);
        g_biasz[d] = a;
    } else if (b == 210) {
        float a = 0.f;
        for (int k = 0; k < 128; k++) a = fmaf(ba[k], Wbb[k*128+d], a);
        g_babb[d] = a;
    } else {
        for (int o = d; o < 520; o += 128) {
            int r = o >> 3, q = o & 7;
            const float* L = (r < 64) ? (Wa + r*128) : ba;
            float a = 0.f;
            for (int k = 0; k < 128; k++) a = fmaf(L[k], Wscore[k*8+q], a);
            if (r < 64) g_Was[r*8+q] = a; else g_bs[q] = a;
        }
    }
}

// ---------------------------------------------------------------------------
// scores = xf @ Was + bs, softmax -> g_nm.  64 nodes / block, 256 threads
// ---------------------------------------------------------------------------
__global__ void nm_kernel(const float* __restrict__ xf) {
    __shared__ float xs[64*65];
    __shared__ float ss[64*8];
    __shared__ float Ws[64*8];
    __shared__ float bs_s[8];
    int tid = threadIdx.x;
    int n0 = blockIdx.x * 64;

    for (int i = tid; i < 64*64; i += 256) {
        int rw = i >> 6, k = i & 63;
        xs[rw*65 + k] = xf[(size_t)(n0 + rw)*64 + k];
    }
    for (int i = tid; i < 64*8; i += 256) Ws[i] = g_Was[i];
    if (tid < 8) bs_s[tid] = g_bs[tid];
    __syncthreads();

    int node = tid >> 2, q = tid & 3;
    float s0 = bs_s[q], s1 = bs_s[q + 4];
    for (int k = 0; k < 64; k++) {
        float a = xs[node*65 + k];
        s0 = fmaf(a, Ws[k*8 + q], s0);
        s1 = fmaf(a, Ws[k*8 + q + 4], s1);
    }
    ss[node*8 + q]     = s0;
    ss[node*8 + q + 4] = s1;
    __syncthreads();

    if (tid < 128) {
        int nd = tid >> 1, r = tid & 1;
        float v[4];
#pragma unroll
        for (int c = 0; c < 4; c++) v[c] = ss[nd*8 + c*2 + r];
        float m = fmaxf(fmaxf(v[0], v[1]), fmaxf(v[2], v[3]));
        float e[4], sum = 0.f;
#pragma unroll
        for (int c = 0; c < 4; c++) { e[c] = expf(v[c] - m); sum += e[c]; }
        float inv = 1.f / sum;
        int n = n0 + nd;
#pragma unroll
        for (int c = 0; c < 4; c++)
            g_nm[(size_t)(r*4 + c)*NN + n] = e[c] * inv;
    }
}

// ---------------------------------------------------------------------------
// Per-graph fused kernel.  1 block / graph, 256 threads.
// ---------------------------------------------------------------------------
__global__ void graph_kernel(const float* __restrict__ x,
                             const float* __restrict__ h,
                             const float* __restrict__ xf,
                             const float* __restrict__ edge_attr,
                             const int* __restrict__ ei) {
    extern __shared__ float smf[];
    float* nm_sm   = smf;             // 2048
    float* srcw    = nm_sm + 2048;    // 2048
    float* ea_sm   = srcw + 2048;     // 4096
    float* wnum_c  = ea_sm + 4096;    // 2048
    float* numh_sm = wnum_c + 2048;   // 1024
    float* bc_sm   = numh_sm + 1024;  // 1024
    float* red_sm  = bc_sm + 1024;    // 256
    float* w_sm    = red_sm + 256;    // 24
    float* den_sm  = w_sm + 24;       // 8
    int* sl  = (int*)(den_sm + 8);    // 1024
    int* dl  = sl + 1024;             // 1024
    int* deg = dl + 1024;             // 256
    int* off = deg + 256;             // 257
    int* cur = off + 257;             // 256
    int* csr = cur + 256;             // 1024

    const int g = blockIdx.x;
    const int tid = threadIdx.x;
    const int gb = g * PN;
    const int ge = g * EPG;

    for (int i = tid; i < PN; i += 256) deg[i] = 0;
    if (tid < 20) w_sm[tid] = 0.f;
    for (int i = tid; i < 2048; i += 256) {
        srcw[i] = 0.f;
        nm_sm[i] = g_nm[(size_t)(i >> 8)*NN + gb + (i & 255)];
    }
    __syncthreads();

    float wp[20];
#pragma unroll
    for (int p = 0; p < 20; p++) wp[p] = 0.f;
    float nacc = 0.f;
    const int eh = tid >> 7, rcb = (tid >> 4) & 7, qb = tid & 15;

    for (int c0 = 0; c0 < EPG; c0 += 256) {
        int e = c0 + tid;
        int s = ei[ge + e] - gb;
        int d = ei[NE + ge + e] - gb;
        sl[e] = s; dl[e] = d;
        atomicAdd(&deg[d], 1);
        const float4* earow = (const float4*)(edge_attr + (size_t)(ge + e)*16);
        float4* eadst = (float4*)(ea_sm + tid*16);
        eadst[0] = earow[0]; eadst[1] = earow[1];
        eadst[2] = earow[2]; eadst[3] = earow[3];

        float ns[8], nd[8];
#pragma unroll
        for (int rc = 0; rc < 8; rc++) {
            ns[rc] = nm_sm[rc*256 + s];
            nd[rc] = nm_sm[rc*256 + d];
            float wv = nd[rc]*nd[rc]*ns[rc];
            wnum_c[tid*8 + rc] = wv;
            atomicAdd(&srcw[rc*256 + s], wv);
        }
#pragma unroll
        for (int r = 0; r < 2; r++) {
            int b = r*4, w0 = r*10;
            wp[w0+0] += ns[b+0]*nd[b+1];
            wp[w0+1] += ns[b+0]*nd[b+2];
            wp[w0+2] += ns[b+0]*nd[b+3];
            wp[w0+3] += ns[b+1]*nd[b+2];
            wp[w0+4] += ns[b+1]*nd[b+3];
            wp[w0+5] += ns[b+2]*nd[b+3];
#pragma unroll
            for (int c = 0; c < 4; c++) wp[w0+6+c] += ns[b+c]*nd[b+c];
        }
        __syncthreads();
        for (int el = eh*128; el < eh*128 + 128; el++)
            nacc = fmaf(wnum_c[el*8 + rcb], ea_sm[el*16 + qb], nacc);
        __syncthreads();
    }

    red_sm[tid] = nacc;
    __syncthreads();
    if (tid < 128) {
        float v = red_sm[tid] + red_sm[tid + 128];
        int rc = tid >> 4, q = tid & 15;
        int r = rc >> 2, c = rc & 3;
        g_numea[((size_t)(r*NG + g)*4 + c)*16 + q] = v;
    }

#pragma unroll
    for (int p = 0; p < 20; p++)
        for (int o = 16; o > 0; o >>= 1)
            wp[p] += __shfl_down_sync(0xffffffffu, wp[p], o);
    if ((tid & 31) == 0)
#pragma unroll
        for (int p = 0; p < 20; p++) atomicAdd(&w_sm[p], wp[p]);
    __syncthreads();

    if (tid == 0) {
        int a = 0;
        for (int i = 0; i < PN; i++) { off[i] = a; a += deg[i]; }
        off[PN] = a;
    }
    __syncthreads();
    for (int i = tid; i < PN; i += 256) cur[i] = off[i];
    __syncthreads();
    for (int e = tid; e < EPG; e += 256) {
        int pos = atomicAdd(&cur[dl[e]], 1);
        csr[pos] = e;
    }
    __syncthreads();

    if (tid < PN) g_deg[gb + tid] = (float)deg[tid];

    // aggea via CSR: thread = (node, q)
    for (int i = tid; i < PN*16; i += 256) {
        int nl = i >> 4, q = i & 15;
        float a = 0.f;
        int e0 = off[nl], e1 = off[nl + 1];
        for (int ii = e0; ii < e1; ii++)
            a += edge_attr[(size_t)(ge + csr[ii])*16 + q];
        g_aggea[(size_t)(gb + nl)*16 + q] = a;
    }

    // aggxf via CSR: thread = (quarter, d64)
    {
        const int d64 = tid & 63, qtr = tid >> 6;
        for (int nl = qtr; nl < PN; nl += 4) {
            float a = 0.f;
            int e0 = off[nl], e1 = off[nl + 1];
            for (int ii = e0; ii < e1; ii++)
                a += xf[(size_t)(gb + sl[csr[ii]])*64 + d64];
            g_aggxf[(size_t)(gb + nl)*64 + d64] = a;
        }
    }

    // ---- vector phase: thread = (d, half) ----
    const int d = tid & 127, half = tid >> 7;
    float numa[8], bca[8];
#pragma unroll
    for (int rc = 0; rc < 8; rc++) { numa[rc] = 0.f; bca[rc] = 0.f; }

    for (int nl = half; nl < PN; nl += 2) {
        float xv = x[(size_t)(gb + nl)*128 + d];
        float hv = h[(size_t)(gb + nl)*128 + d];
#pragma unroll
        for (int rc = 0; rc < 8; rc++) {
            float w1 = nm_sm[rc*256 + nl];
            numa[rc] = fmaf(w1 + srcw[rc*256 + nl], hv, numa[rc]);
            bca[rc]  = fmaf(w1, xv, bca[rc]);
        }
    }

    if (half == 0)
#pragma unroll
        for (int rc = 0; rc < 8; rc++) {
            numh_sm[rc*128 + d] = numa[rc];
            bc_sm[rc*128 + d]   = bca[rc];
        }
    __syncthreads();
    if (half == 1)
#pragma unroll
        for (int rc = 0; rc < 8; rc++) {
            numh_sm[rc*128 + d] += numa[rc];
            bc_sm[rc*128 + d]   += bca[rc];
        }
    __syncthreads();

    if (tid < 8) {
        float s = 0.f;
        for (int n = 0; n < PN; n++) s += nm_sm[tid*256 + n];
        den_sm[tid] = s + 1e-6f;
    }
    __syncthreads();

    for (int i = tid; i < 8*128; i += 256) {
        int rc = i >> 7, dd = i & 127;
        int r = rc >> 2, c = rc & 3;
        size_t o = ((size_t)(r*NG + g)*4 + c)*128 + dd;
        g_numh[o]  = numh_sm[rc*128 + dd];
        g_aggbc[o] = bc_sm[rc*128 + dd];
    }
    if (tid < 8) {
        int r = tid >> 2, c = tid & 3;
        g_den[(size_t)(r*NG + g)*4 + c] = den_sm[tid];
    }

    if (tid < 32) {
        const int pidx[4][4] = { {6,0,1,2}, {0,7,3,4}, {1,3,8,5}, {2,4,5,9} };
        int r = tid >> 4, idx = tid & 15;
        int i = idx >> 2, j = idx & 3;
        float v = w_sm[r*10 + pidx[i][j]];
        if (i == j) v *= 0.5f;
        g_Wccraw[(r*NG + g)*16 + idx] = v;
    }
}

// ---------------------------------------------------------------------------
__global__ void maxred_kernel() {
    __shared__ float red[256];
    int tid = threadIdx.x;
    float m = 0.f;
    for (int i = tid; i < 2*NG*16; i += 256) m = fmaxf(m, g_Wccraw[i]);
    red[tid] = m; __syncthreads();
    for (int s = 128; s > 0; s >>= 1) {
        if (tid < s) red[tid] = fmaxf(red[tid], red[tid + s]);
        __syncthreads();
    }
    if (tid == 0) g_maxplus = red[0] + 1e-9f;
}

// ---------------------------------------------------------------------------
// per (r,g): cent_x, cc, h_cent, hcw.  grid = 2*NG, 128 threads
// ---------------------------------------------------------------------------
__global__ void hcent_kernel(const float* __restrict__ Wedge,
                             const float* __restrict__ Wbc,
                             const float* __restrict__ Wcc_,
                             const float* __restrict__ Wsc,
                             const float* __restrict__ Wcb) {
    __shared__ float We[16*128], cx[512], bc[512], cc[512], hc[512];
    __shared__ float numea[64], Wg[16], den[4];
    int b = blockIdx.x;
    int d = threadIdx.x;
    size_t base = (size_t)b * 512;

    for (int i = d; i < 2048; i += 128) We[i] = Wedge[i];
    for (int i = d; i < 512; i += 128) {
        cx[i] = g_numh[base + i];
        bc[i] = g_aggbc[base + i];
    }
    if (d < 64) numea[d] = g_numea[(size_t)b*64 + d];
    if (d < 16) Wg[d] = g_Wccraw[b*16 + d] / g_maxplus;
    if (d < 4)  den[d] = g_den[(size_t)b*4 + d];
    __syncthreads();

#pragma unroll
    for (int c = 0; c < 4; c++) {
        float v = cx[c*128 + d];
#pragma unroll
        for (int q = 0; q < 16; q++)
            v = fmaf(numea[c*16 + q], We[q*128 + d], v);
        cx[c*128 + d] = v / den[c];
    }
    __syncthreads();
#pragma unroll
    for (int c = 0; c < 4; c++) {
        float a = 0.f;
#pragma unroll
        for (int j = 0; j < 4; j++) a = fmaf(Wg[c*4 + j], cx[j*128 + d], a);
        cc[c*128 + d] = a;
    }
    __syncthreads();
    float acc[4] = {0.f, 0.f, 0.f, 0.f};
    for (int k = 0; k < 128; k++) {
        float wb = Wbc[k*128 + d], wc = Wcc_[k*128 + d], ws = Wsc[k*128 + d];
#pragma unroll
        for (int c = 0; c < 4; c++) {
            acc[c] = fmaf(bc[c*128 + k], wb, acc[c]);
            acc[c] = fmaf(cc[c*128 + k], wc, acc[c]);
            acc[c] = fmaf(cx[c*128 + k], ws, acc[c]);
        }
    }
#pragma unroll
    for (int c = 0; c < 4; c++) hc[c*128 + d] = fmaxf(acc[c], 0.f);
    __syncthreads();
    float o[4] = {0.f, 0.f, 0.f, 0.f};
    for (int k = 0; k < 128; k++) {
        float w = Wcb[k*128 + d];
#pragma unroll
        for (int c = 0; c < 4; c++) o[c] = fmaf(hc[c*128 + k], w, o[c]);
    }
#pragma unroll
    for (int c = 0; c < 4; c++) g_hcw[base + c*128 + d] = o[c];
}

// ---------------------------------------------------------------------------
// Final fused: node = mean_r relu(Z + Sum_c nm*hcw); pool; heads.  grid = NG
// ---------------------------------------------------------------------------
__global__ void final_kernel(const float* __restrict__ W_inter,
                             const float* __restrict__ b_inter,
                             const float* __restrict__ W_out,
                             const float* __restrict__ b_out,
                             float* __restrict__ out) {
    __shared__ float hcw[1024], nm_s[2048], red[256], gs[128], emb[128];
    int g = blockIdx.x, tid = threadIdx.x;
    for (int i = tid; i < 1024; i += 256) {
        int r = i >> 9;
        hcw[i] = g_hcw[(size_t)(r*NG + g)*512 + (i & 511)];
    }
    for (int i = tid; i < 2048; i += 256)
        nm_s[i] = g_nm[(size_t)(i >> 8)*NN + g*PN + (i & 255)];
    __syncthreads();

    int d = tid & 127, half = tid >> 7;
    float acc = 0.f;
    for (int nl = half; nl < PN; nl += 2) {
        float z = g_Z[(size_t)(g*PN + nl)*128 + d];
        float y0 = 0.f, y1 = 0.f;
#pragma unroll
        for (int c = 0; c < 4; c++) {
            y0 = fmaf(nm_s[c*256 + nl],       hcw[c*128 + d],       y0);
            y1 = fmaf(nm_s[(4 + c)*256 + nl], hcw[512 + c*128 + d], y1);
        }
        acc += 0.5f * (fmaxf(z + y0, 0.f) + fmaxf(z + y1, 0.f));
    }
    red[tid] = acc;
    __syncthreads();
    if (tid < 128) gs[tid] = (red[tid] + red[tid + 128]) * (1.0f / PN);
    __syncthreads();
    if (tid < 128) {
        float e = b_inter[tid];
        for (int k = 0; k < 128; k++) e = fmaf(gs[k], W_inter[k*128 + tid], e);
        emb[tid] = e;
    }
    __syncthreads();
    if (tid < OUTD) {
        float o = b_out[tid];
        for (int k = 0; k < 128; k++) o = fmaf(emb[k], W_out[k*OUTD + tid], o);
        out[g*OUTD + tid] = o;
    }
}

// ---------------------------------------------------------------------------
extern "C" void kernel_launch(void* const* d_in, const int* in_sizes, int n_in,
                              void* d_out, int out_size) {
    const float* x_feat    = (const float*)d_in[0];
    const float* edge_attr = (const float*)d_in[1];
    const float* W_atom    = (const float*)d_in[2];
    const float* b_atom    = (const float*)d_in[3];
    const float* W_score   = (const float*)d_in[4];
    const float* W_edge    = (const float*)d_in[5];
    const float* W_b2c     = (const float*)d_in[6];
    const float* W_bb      = (const float*)d_in[7];
    const float* W_bc      = (const float*)d_in[8];
    const float* W_cb      = (const float*)d_in[9];
    const float* W_cc      = (const float*)d_in[10];
    const float* W_sb      = (const float*)d_in[11];
    const float* W_sc      = (const float*)d_in[12];
    const float* W_inter   = (const float*)d_in[13];
    const float* b_inter   = (const float*)d_in[14];
    const float* W_out     = (const float*)d_in[15];
    const float* b_out     = (const float*)d_in[16];
    const int*   edge_index= (const int*)d_in[17];
    float* out = (float*)d_out;

    cudaFuncSetAttribute(gemm128, cudaFuncAttributeMaxDynamicSharedMemorySize, 95000);
    cudaFuncSetAttribute(graph_kernel, cudaFuncAttributeMaxDynamicSharedMemorySize, 66000);

    void *px_, *ph_, *pxf_, *pea_, *pZ_, *pdeg_;
    void *pWab_, *pWasb_, *pWawbb_, *pW3_, *pbh_, *pbz_, *pbabb_;
    cudaGetSymbolAddress(&px_,  g_x);
    cudaGetSymbolAddress(&ph_,  g_h);
    cudaGetSymbolAddress(&pxf_, g_aggxf);
    cudaGetSymbolAddress(&pea_, g_aggea);
    cudaGetSymbolAddress(&pZ_,  g_Z);
    cudaGetSymbolAddress(&pdeg_, g_deg);
    cudaGetSymbolAddress(&pWab_, g_Wab);
    cudaGetSymbolAddress(&pWasb_, g_Wasb);
    cudaGetSymbolAddress(&pWawbb_, g_Wawbb);
    cudaGetSymbolAddress(&pW3_, g_W3);
    cudaGetSymbolAddress(&pbh_, g_biash);
    cudaGetSymbolAddress(&pbz_, g_biasz);
    cudaGetSymbolAddress(&pbabb_, g_babb);
    float* px    = (float*)px_;
    float* ph    = (float*)ph_;
    float* paxf  = (float*)pxf_;
    float* pea   = (float*)pea_;
    float* pZ    = (float*)pZ_;
    float* pdeg  = (float*)pdeg_;
    float* pWab  = (float*)pWab_;
    float* pWasb = (float*)pWasb_;
    float* pWawbb= (float*)pWawbb_;
    float* pW3   = (float*)pW3_;
    float* pbh   = (float*)pbh_;
    float* pbz   = (float*)pbz_;
    float* pbabb = (float*)pbabb_;

    const size_t smA = 128*17*8;   // 17408 (packed u64 A tile)

    // 1. fused weights (parallel, ~2us)
    prep_big<<<212, 128>>>(W_atom, b_atom, W_b2c, W_sb, W_bb, W_edge, W_score);
    // 2. x = x_feat @ W_atom + b_atom          (K=64)
    gemm128<<<NN/128, 256, 64*512 + smA>>>(
        x_feat, W_atom, 64, nullptr, nullptr, 0, nullptr, nullptr, 0,
        b_atom, nullptr, nullptr, 0, px);
    // 3. nm (scores from x_feat via fused Was)
    nm_kernel<<<NN/64, 256>>>(x_feat);
    // 4. h = relu(x_feat @ Wab + biash)        (K=64)
    gemm128<<<NN/128, 256, 64*512 + smA>>>(
        x_feat, pWab, 64, nullptr, nullptr, 0, nullptr, nullptr, 0,
        pbh, nullptr, nullptr, 1, ph);
    // 5. per-graph fused pass
    graph_kernel<<<NG, 256, 65668>>>(px, ph, x_feat, edge_attr, edge_index);
    // 6. max for Wcc normalization
    maxred_kernel<<<1, 256>>>();
    // 7. h_cent + hcw
    hcent_kernel<<<2*NG, 128>>>(W_edge, W_bc, W_cc, W_sc, W_cb);
    // 8. Z = aggxf@Wawbb + xf@Wasb + aggea@W3 + biasz + deg*babb   (K=144)
    gemm128<<<NN/128, 256, (64+64+16)*512 + smA>>>(
        paxf, pWawbb, 64, x_feat, pWasb, 64, pea, pW3, 16,
        pbz, pdeg, pbabb, 0, pZ);
    // 9. fused Y + relu + mean + pool + heads
    final_kernel<<<NG, 256>>>(W_inter, b_inter, W_out, b_out, out);
}

// round 5
// speedup vs baseline: 2.7914x; 1.2257x over previous
#include <cuda_runtime.h>
#include <math.h>

#define NG   128
#define PN   256
#define EPG  1024
#define NN   (NG*PN)     // 32768
#define NE   (NG*EPG)    // 131072
#define DD   128
#define OUTD 10

// ---------------- device scratch ----------------
__device__ float g_x[NN*DD];
__device__ float g_h[NN*DD];
__device__ float g_nm[8*NN];              // [(r*4+c)*NN + n]
__device__ float g_aggxf[NN*64];          // CSR-gathered x_feat
__device__ float g_deg[NN];
__device__ float g_aggea[NN*16];          // edge_attr scatter
__device__ float g_numh[2*NG*4*DD];
__device__ float g_aggbc[2*NG*4*DD];
__device__ float g_den[2*NG*4];
__device__ float g_numea[2*NG*4*16];
__device__ float g_Wccraw[2*NG*16];
__device__ float g_maxplus;
__device__ float g_hcw[2*NG*4*DD];
__device__ float g_Z[NN*DD];
// fused weights
__device__ float g_Wab[64*128];           // Wa@W_b2c
__device__ float g_Wasb[64*128];          // Wa@W_sb
__device__ float g_Wawbb[64*128];         // Wa@W_bb
__device__ float g_W3[16*128];            // We@W_bb
__device__ float g_biash[128];            // ba@W_b2c
__device__ float g_biasz[128];            // ba@W_sb
__device__ float g_babb[128];             // ba@W_bb
__device__ float g_Was[64*8];             // Wa@W_score
__device__ float g_bs[8];                 // ba@W_score

// ---------------- packed f32x2 helpers ----------------
typedef unsigned long long u64t;
__device__ __forceinline__ u64t pk2(float lo, float hi) {
    u64t r; asm("mov.b64 %0, {%1,%2};" : "=l"(r) : "f"(lo), "f"(hi)); return r;
}
__device__ __forceinline__ void upk2(u64t v, float& lo, float& hi) {
    asm("mov.b64 {%0,%1}, %2;" : "=f"(lo), "=f"(hi) : "l"(v));
}
__device__ __forceinline__ void fma2(u64t& d, u64t a, u64t b) {
    asm("fma.rn.f32x2 %0, %1, %2, %0;" : "+l"(d) : "l"(a), "l"(b));
}

// ---------------------------------------------------------------------------
// 128-col fp32 GEMM, packed f32x2 FMA, A staged pre-packed {a,a} in shared.
// __launch_bounds__(256,2) -> <=128 regs -> 2 blocks/SM.
// ---------------------------------------------------------------------------
__device__ __forceinline__ void mma_pass2(const float* __restrict__ A, int K,
                                          const float* __restrict__ Ws,
                                          u64t* As, int row0, int tid,
                                          int tr, int tc2, u64t acc[8][4]) {
    float4 pre[2];
#pragma unroll
    for (int it = 0; it < 2; it++) {
        int idx = tid + it*256; int lr = idx >> 2, lc = (idx & 3) * 4;
        pre[it] = *(const float4*)(A + (size_t)(row0 + lr)*K + lc);
    }
    for (int k0 = 0; k0 < K; k0 += 16) {
        __syncthreads();
#pragma unroll
        for (int it = 0; it < 2; it++) {
            int idx = tid + it*256; int lr = idx >> 2, lc = (idx & 3) * 4;
            float4 v = pre[it];
            As[lr*17 + lc + 0] = pk2(v.x, v.x);
            As[lr*17 + lc + 1] = pk2(v.y, v.y);
            As[lr*17 + lc + 2] = pk2(v.z, v.z);
            As[lr*17 + lc + 3] = pk2(v.w, v.w);
        }
        __syncthreads();
        if (k0 + 16 < K) {
#pragma unroll
            for (int it = 0; it < 2; it++) {
                int idx = tid + it*256; int lr = idx >> 2, lc = (idx & 3) * 4;
                pre[it] = *(const float4*)(A + (size_t)(row0 + lr)*K + k0 + 16 + lc);
            }
        }
#pragma unroll
        for (int kk = 0; kk < 16; kk++) {
            const float* wrow = Ws + (k0 + kk)*128;
            u64t wv[4];
#pragma unroll
            for (int jp = 0; jp < 4; jp++)
                wv[jp] = *(const u64t*)(wrow + tc2 + 32*jp);
#pragma unroll
            for (int i = 0; i < 8; i++) {
                u64t ap = As[(tr + 16*i)*17 + kk];
#pragma unroll
                for (int jp = 0; jp < 4; jp++) fma2(acc[i][jp], ap, wv[jp]);
            }
        }
    }
}

__global__ void __launch_bounds__(256, 2)
gemm128(const float* __restrict__ A1, const float* __restrict__ W1, int K1,
        const float* __restrict__ A2, const float* __restrict__ W2, int K2,
        const float* __restrict__ A3, const float* __restrict__ W3, int K3,
        const float* __restrict__ bias,
        const float* __restrict__ rowscale,
        const float* __restrict__ rowvec,
        int relu_flag,
        float* __restrict__ out) {
    extern __shared__ float sm[];
    float* Ws1 = sm;
    float* Ws2 = Ws1 + K1*128;
    float* Ws3 = Ws2 + K2*128;
    u64t*  As  = (u64t*)(Ws3 + K3*128);

    const int tid = threadIdx.x;
    const int tr = tid >> 4, tc2 = (tid & 15) * 2;
    const int row0 = blockIdx.x * 128;

    for (int i = tid*4; i < K1*128; i += 1024) *(float4*)(Ws1+i) = *(const float4*)(W1+i);
    if (A2) for (int i = tid*4; i < K2*128; i += 1024) *(float4*)(Ws2+i) = *(const float4*)(W2+i);
    if (A3) for (int i = tid*4; i < K3*128; i += 1024) *(float4*)(Ws3+i) = *(const float4*)(W3+i);

    u64t acc[8][4];
#pragma unroll
    for (int i = 0; i < 8; i++)
#pragma unroll
        for (int j = 0; j < 4; j++) acc[i][j] = 0ull;

    mma_pass2(A1, K1, Ws1, As, row0, tid, tr, tc2, acc);
    if (A2) mma_pass2(A2, K2, Ws2, As, row0, tid, tr, tc2, acc);
    if (A3) mma_pass2(A3, K3, Ws3, As, row0, tid, tr, tc2, acc);

#pragma unroll
    for (int i = 0; i < 8; i++) {
        int row = row0 + tr + 16*i;
        float rs = rowscale ? rowscale[row] : 0.f;
#pragma unroll
        for (int jp = 0; jp < 4; jp++) {
            int cb = tc2 + 32*jp;
            float lo, hi; upk2(acc[i][jp], lo, hi);
            if (bias)   { lo += bias[cb];        hi += bias[cb+1]; }
            if (rowvec) { lo += rs * rowvec[cb]; hi += rs * rowvec[cb+1]; }
            if (relu_flag) { lo = fmaxf(lo, 0.f); hi = fmaxf(hi, 0.f); }
            out[(size_t)row*128 + cb]     = lo;
            out[(size_t)row*128 + cb + 1] = hi;
        }
    }
}

// ---------------------------------------------------------------------------
// Parallel weight precompute.  grid = 212 blocks x 128 threads.
// ---------------------------------------------------------------------------
__global__ void prep_big(const float* __restrict__ Wa, const float* __restrict__ ba,
                         const float* __restrict__ Wb2c, const float* __restrict__ Wsb,
                         const float* __restrict__ Wbb, const float* __restrict__ We,
                         const float* __restrict__ Wscore) {
    int b = blockIdx.x, d = threadIdx.x;
    if (b < 64) {
        float a = 0.f;
        for (int k = 0; k < 128; k++) a = fmaf(Wa[b*128+k], Wb2c[k*128+d], a);
        g_Wab[b*128+d] = a;
    } else if (b < 128) {
        int f = b - 64; float a = 0.f;
        for (int k = 0; k < 128; k++) a = fmaf(Wa[f*128+k], Wsb[k*128+d], a);
        g_Wasb[f*128+d] = a;
    } else if (b < 144) {
        int q = b - 128; float a = 0.f;
        for (int k = 0; k < 128; k++) a = fmaf(We[q*128+k], Wbb[k*128+d], a);
        g_W3[q*128+d] = a;
    } else if (b < 208) {
        int f = b - 144; float a = 0.f;
        for (int k = 0; k < 128; k++) a = fmaf(Wa[f*128+k], Wbb[k*128+d], a);
        g_Wawbb[f*128+d] = a;
    } else if (b == 208) {
        float a = 0.f;
        for (int k = 0; k < 128; k++) a = fmaf(ba[k], Wb2c[k*128+d], a);
        g_biash[d] = a;
    } else if (b == 209) {
        float a = 0.f;
        for (int k = 0; k < 128; k++) a = fmaf(ba[k], Wsb[k*128+d], a);
        g_biasz[d] = a;
    } else if (b == 210) {
        float a = 0.f;
        for (int k = 0; k < 128; k++) a = fmaf(ba[k], Wbb[k*128+d], a);
        g_babb[d] = a;
    } else {
        for (int o = d; o < 520; o += 128) {
            int r = o >> 3, q = o & 7;
            const float* L = (r < 64) ? (Wa + r*128) : ba;
            float a = 0.f;
            for (int k = 0; k < 128; k++) a = fmaf(L[k], Wscore[k*8+q], a);
            if (r < 64) g_Was[r*8+q] = a; else g_bs[q] = a;
        }
    }
}

// ---------------------------------------------------------------------------
// scores = xf @ Was + bs, softmax -> g_nm.  64 nodes / block, 256 threads
// ---------------------------------------------------------------------------
__global__ void nm_kernel(const float* __restrict__ xf) {
    __shared__ float xs[64*65];
    __shared__ float ss[64*8];
    __shared__ float Ws[64*8];
    __shared__ float bs_s[8];
    int tid = threadIdx.x;
    int n0 = blockIdx.x * 64;

    for (int i = tid; i < 64*64; i += 256) {
        int rw = i >> 6, k = i & 63;
        xs[rw*65 + k] = xf[(size_t)(n0 + rw)*64 + k];
    }
    for (int i = tid; i < 64*8; i += 256) Ws[i] = g_Was[i];
    if (tid < 8) bs_s[tid] = g_bs[tid];
    __syncthreads();

    int node = tid >> 2, q = tid & 3;
    float s0 = bs_s[q], s1 = bs_s[q + 4];
    for (int k = 0; k < 64; k++) {
        float a = xs[node*65 + k];
        s0 = fmaf(a, Ws[k*8 + q], s0);
        s1 = fmaf(a, Ws[k*8 + q + 4], s1);
    }
    ss[node*8 + q]     = s0;
    ss[node*8 + q + 4] = s1;
    __syncthreads();

    if (tid < 128) {
        int nd = tid >> 1, r = tid & 1;
        float v[4];
#pragma unroll
        for (int c = 0; c < 4; c++) v[c] = ss[nd*8 + c*2 + r];
        float m = fmaxf(fmaxf(v[0], v[1]), fmaxf(v[2], v[3]));
        float e[4], sum = 0.f;
#pragma unroll
        for (int c = 0; c < 4; c++) { e[c] = expf(v[c] - m); sum += e[c]; }
        float inv = 1.f / sum;
        int n = n0 + nd;
#pragma unroll
        for (int c = 0; c < 4; c++)
            g_nm[(size_t)(r*4 + c)*NN + n] = e[c] * inv;
    }
}

// ---------------------------------------------------------------------------
// Per-graph fused kernel.  1 block / graph, 512 threads.
// ---------------------------------------------------------------------------
__global__ void __launch_bounds__(512)
graph_kernel(const float* __restrict__ x,
             const float* __restrict__ h,
             const float* __restrict__ xf,
             const float* __restrict__ edge_attr,
             const int* __restrict__ ei) {
    extern __shared__ float smf[];
    float* nm_sm   = smf;             // 2048
    float* srcw    = nm_sm + 2048;    // 2048
    float* ea_sm   = srcw + 2048;     // 8192  (chunk: 512 edges x 16)
    float* wnum_c  = ea_sm + 8192;    // 4096  (chunk: 512 x 8)
    float* numh_sm = wnum_c + 4096;   // 1024
    float* bc_sm   = numh_sm + 1024;  // 1024
    float* red_sm  = bc_sm + 1024;    // 512
    float* w_sm    = red_sm + 512;    // 24
    float* den_sm  = w_sm + 24;       // 8
    int* sl  = (int*)(den_sm + 8);    // 1024
    int* dl  = sl + 1024;             // 1024
    int* deg = dl + 1024;             // 256
    int* off = deg + 256;             // 257
    int* cur = off + 257;             // 256
    int* csr = cur + 256;             // 1024

    const int g = blockIdx.x;
    const int tid = threadIdx.x;
    const int gb = g * PN;
    const int ge = g * EPG;

    for (int i = tid; i < PN; i += 512) deg[i] = 0;
    if (tid < 20) w_sm[tid] = 0.f;
    for (int i = tid; i < 2048; i += 512) {
        srcw[i] = 0.f;
        nm_sm[i] = g_nm[(size_t)(i >> 8)*NN + gb + (i & 255)];
    }
    __syncthreads();

    float wp[20];
#pragma unroll
    for (int p = 0; p < 20; p++) wp[p] = 0.f;
    float nacc = 0.f;
    const int eh = tid >> 7, rcb = (tid >> 4) & 7, qb = tid & 15;

    for (int c0 = 0; c0 < EPG; c0 += 512) {
        int e = c0 + tid;
        int s = ei[ge + e] - gb;
        int d = ei[NE + ge + e] - gb;
        sl[e] = s; dl[e] = d;
        atomicAdd(&deg[d], 1);
        const float4* earow = (const float4*)(edge_attr + (size_t)(ge + e)*16);
        float4* eadst = (float4*)(ea_sm + tid*16);
        eadst[0] = earow[0]; eadst[1] = earow[1];
        eadst[2] = earow[2]; eadst[3] = earow[3];

        float ns[8], nd[8];
#pragma unroll
        for (int rc = 0; rc < 8; rc++) {
            ns[rc] = nm_sm[rc*256 + s];
            nd[rc] = nm_sm[rc*256 + d];
            float wv = nd[rc]*nd[rc]*ns[rc];
            wnum_c[tid*8 + rc] = wv;
            atomicAdd(&srcw[rc*256 + s], wv);
        }
#pragma unroll
        for (int r = 0; r < 2; r++) {
            int b = r*4, w0 = r*10;
            wp[w0+0] += ns[b+0]*nd[b+1];
            wp[w0+1] += ns[b+0]*nd[b+2];
            wp[w0+2] += ns[b+0]*nd[b+3];
            wp[w0+3] += ns[b+1]*nd[b+2];
            wp[w0+4] += ns[b+1]*nd[b+3];
            wp[w0+5] += ns[b+2]*nd[b+3];
#pragma unroll
            for (int c = 0; c < 4; c++) wp[w0+6+c] += ns[b+c]*nd[b+c];
        }
        __syncthreads();
        // numea partial: thread = (eh in 0..3, rc, q); 128 edges each
        for (int el = eh*128; el < eh*128 + 128; el++)
            nacc = fmaf(wnum_c[el*8 + rcb], ea_sm[el*16 + qb], nacc);
        __syncthreads();
    }

    red_sm[tid] = nacc;
    __syncthreads();
    if (tid < 128) {
        float v = red_sm[tid] + red_sm[tid + 128] + red_sm[tid + 256] + red_sm[tid + 384];
        int rc = tid >> 4, q = tid & 15;
        int r = rc >> 2, c = rc & 3;
        g_numea[((size_t)(r*NG + g)*4 + c)*16 + q] = v;
    }

#pragma unroll
    for (int p = 0; p < 20; p++)
        for (int o = 16; o > 0; o >>= 1)
            wp[p] += __shfl_down_sync(0xffffffffu, wp[p], o);
    if ((tid & 31) == 0)
#pragma unroll
        for (int p = 0; p < 20; p++) atomicAdd(&w_sm[p], wp[p]);
    __syncthreads();

    // exclusive prefix sum of deg via warp-shuffle scan (warp 0)
    if (tid < 32) {
        int run = 0;
        for (int seg = 0; seg < 8; seg++) {
            int dv = deg[seg*32 + tid];
            int v = dv;
#pragma unroll
            for (int o = 1; o < 32; o <<= 1) {
                int t = __shfl_up_sync(0xffffffffu, v, o);
                if ((tid & 31) >= o) v += t;
            }
            off[seg*32 + tid] = run + v - dv;
            run += __shfl_sync(0xffffffffu, v, 31);
        }
        if (tid == 31) off[PN] = run;
    }
    __syncthreads();
    for (int i = tid; i < PN; i += 512) cur[i] = off[i];
    __syncthreads();
    for (int e = tid; e < EPG; e += 512) {
        int pos = atomicAdd(&cur[dl[e]], 1);
        csr[pos] = e;
    }
    __syncthreads();

    if (tid < PN) g_deg[gb + tid] = (float)deg[tid];

    // aggea via CSR: thread = (node, q)
    for (int i = tid; i < PN*16; i += 512) {
        int nl = i >> 4, q = i & 15;
        float a = 0.f;
        int e0 = off[nl], e1 = off[nl + 1];
        for (int ii = e0; ii < e1; ii++)
            a += edge_attr[(size_t)(ge + csr[ii])*16 + q];
        g_aggea[(size_t)(gb + nl)*16 + q] = a;
    }

    // aggxf via CSR: thread = (grp of 8, d64)
    {
        const int d64 = tid & 63, grp = tid >> 6;
        for (int nl = grp; nl < PN; nl += 8) {
            float a = 0.f;
            int e0 = off[nl], e1 = off[nl + 1];
            for (int ii = e0; ii < e1; ii++)
                a += xf[(size_t)(gb + sl[csr[ii]])*64 + d64];
            g_aggxf[(size_t)(gb + nl)*64 + d64] = a;
        }
    }

    // ---- vector phase: thread = (d, quarter) ----
    const int d = tid & 127, q4 = tid >> 7;
    float numa[8], bca[8];
#pragma unroll
    for (int rc = 0; rc < 8; rc++) { numa[rc] = 0.f; bca[rc] = 0.f; }

    for (int nl = q4; nl < PN; nl += 4) {
        float xv = x[(size_t)(gb + nl)*128 + d];
        float hv = h[(size_t)(gb + nl)*128 + d];
#pragma unroll
        for (int rc = 0; rc < 8; rc++) {
            float w1 = nm_sm[rc*256 + nl];
            numa[rc] = fmaf(w1 + srcw[rc*256 + nl], hv, numa[rc]);
            bca[rc]  = fmaf(w1, xv, bca[rc]);
        }
    }

    // 4-group sequential reduction into numh_sm/bc_sm
    if (q4 == 0)
#pragma unroll
        for (int rc = 0; rc < 8; rc++) {
            numh_sm[rc*128 + d] = numa[rc];
            bc_sm[rc*128 + d]   = bca[rc];
        }
    __syncthreads();
    if (q4 == 1)
#pragma unroll
        for (int rc = 0; rc < 8; rc++) {
            numh_sm[rc*128 + d] += numa[rc];
            bc_sm[rc*128 + d]   += bca[rc];
        }
    __syncthreads();
    if (q4 == 2)
#pragma unroll
        for (int rc = 0; rc < 8; rc++) {
            numh_sm[rc*128 + d] += numa[rc];
            bc_sm[rc*128 + d]   += bca[rc];
        }
    __syncthreads();
    if (q4 == 3)
#pragma unroll
        for (int rc = 0; rc < 8; rc++) {
            numh_sm[rc*128 + d] += numa[rc];
            bc_sm[rc*128 + d]   += bca[rc];
        }
    __syncthreads();

    if (tid < 8) {
        float s = 0.f;
        for (int n = 0; n < PN; n++) s += nm_sm[tid*256 + n];
        den_sm[tid] = s + 1e-6f;
    }
    __syncthreads();

    for (int i = tid; i < 8*128; i += 512) {
        int rc = i >> 7, dd = i & 127;
        int r = rc >> 2, c = rc & 3;
        size_t o = ((size_t)(r*NG + g)*4 + c)*128 + dd;
        g_numh[o]  = numh_sm[rc*128 + dd];
        g_aggbc[o] = bc_sm[rc*128 + dd];
    }
    if (tid < 8) {
        int r = tid >> 2, c = tid & 3;
        g_den[(size_t)(r*NG + g)*4 + c] = den_sm[tid];
    }

    if (tid < 32) {
        const int pidx[4][4] = { {6,0,1,2}, {0,7,3,4}, {1,3,8,5}, {2,4,5,9} };
        int r = tid >> 4, idx = tid & 15;
        int i = idx >> 2, j = idx & 3;
        float v = w_sm[r*10 + pidx[i][j]];
        if (i == j) v *= 0.5f;
        g_Wccraw[(r*NG + g)*16 + idx] = v;
    }
}

// ---------------------------------------------------------------------------
__global__ void maxred_kernel() {
    __shared__ float red[256];
    int tid = threadIdx.x;
    float m = 0.f;
    for (int i = tid; i < 2*NG*16; i += 256) m = fmaxf(m, g_Wccraw[i]);
    red[tid] = m; __syncthreads();
    for (int s = 128; s > 0; s >>= 1) {
        if (tid < s) red[tid] = fmaxf(red[tid], red[tid + s]);
        __syncthreads();
    }
    if (tid == 0) g_maxplus = red[0] + 1e-9f;
}

// ---------------------------------------------------------------------------
// per (r,g): cent_x, cc, h_cent, hcw.  grid = 2*NG, 128 threads
// ---------------------------------------------------------------------------
__global__ void hcent_kernel(const float* __restrict__ Wedge,
                             const float* __restrict__ Wbc,
                             const float* __restrict__ Wcc_,
                             const float* __restrict__ Wsc,
                             const float* __restrict__ Wcb) {
    __shared__ float We[16*128], cx[512], bc[512], cc[512], hc[512];
    __shared__ float numea[64], Wg[16], den[4];
    int b = blockIdx.x;
    int d = threadIdx.x;
    size_t base = (size_t)b * 512;

    for (int i = d; i < 2048; i += 128) We[i] = Wedge[i];
    for (int i = d; i < 512; i += 128) {
        cx[i] = g_numh[base + i];
        bc[i] = g_aggbc[base + i];
    }
    if (d < 64) numea[d] = g_numea[(size_t)b*64 + d];
    if (d < 16) Wg[d] = g_Wccraw[b*16 + d] / g_maxplus;
    if (d < 4)  den[d] = g_den[(size_t)b*4 + d];
    __syncthreads();

#pragma unroll
    for (int c = 0; c < 4; c++) {
        float v = cx[c*128 + d];
#pragma unroll
        for (int q = 0; q < 16; q++)
            v = fmaf(numea[c*16 + q], We[q*128 + d], v);
        cx[c*128 + d] = v / den[c];
    }
    __syncthreads();
#pragma unroll
    for (int c = 0; c < 4; c++) {
        float a = 0.f;
#pragma unroll
        for (int j = 0; j < 4; j++) a = fmaf(Wg[c*4 + j], cx[j*128 + d], a);
        cc[c*128 + d] = a;
    }
    __syncthreads();
    float acc[4] = {0.f, 0.f, 0.f, 0.f};
    for (int k = 0; k < 128; k++) {
        float wb = Wbc[k*128 + d], wc = Wcc_[k*128 + d], ws = Wsc[k*128 + d];
#pragma unroll
        for (int c = 0; c < 4; c++) {
            acc[c] = fmaf(bc[c*128 + k], wb, acc[c]);
            acc[c] = fmaf(cc[c*128 + k], wc, acc[c]);
            acc[c] = fmaf(cx[c*128 + k], ws, acc[c]);
        }
    }
#pragma unroll
    for (int c = 0; c < 4; c++) hc[c*128 + d] = fmaxf(acc[c], 0.f);
    __syncthreads();
    float o[4] = {0.f, 0.f, 0.f, 0.f};
    for (int k = 0; k < 128; k++) {
        float w = Wcb[k*128 + d];
#pragma unroll
        for (int c = 0; c < 4; c++) o[c] = fmaf(hc[c*128 + k], w, o[c]);
    }
#pragma unroll
    for (int c = 0; c < 4; c++) g_hcw[base + c*128 + d] = o[c];
}

// ---------------------------------------------------------------------------
// Final fused: node = mean_r relu(Z + Sum_c nm*hcw); pool; heads.  grid = NG
// ---------------------------------------------------------------------------
__global__ void final_kernel(const float* __restrict__ W_inter,
                             const float* __restrict__ b_inter,
                             const float* __restrict__ W_out,
                             const float* __restrict__ b_out,
                             float* __restrict__ out) {
    __shared__ float hcw[1024], nm_s[2048], red[512], gs[128], emb[128];
    int g = blockIdx.x, tid = threadIdx.x;
    for (int i = tid; i < 1024; i += 512) {
        int r = i >> 9;
        hcw[i] = g_hcw[(size_t)(r*NG + g)*512 + (i & 511)];
    }
    for (int i = tid; i < 2048; i += 512)
        nm_s[i] = g_nm[(size_t)(i >> 8)*NN + g*PN + (i & 255)];
    __syncthreads();

    int d = tid & 127, q4 = tid >> 7;
    float acc = 0.f;
    for (int nl = q4; nl < PN; nl += 4) {
        float z = g_Z[(size_t)(g*PN + nl)*128 + d];
        float y0 = 0.f, y1 = 0.f;
#pragma unroll
        for (int c = 0; c < 4; c++) {
            y0 = fmaf(nm_s[c*256 + nl],       hcw[c*128 + d],       y0);
            y1 = fmaf(nm_s[(4 + c)*256 + nl], hcw[512 + c*128 + d], y1);
        }
        acc += 0.5f * (fmaxf(z + y0, 0.f) + fmaxf(z + y1, 0.f));
    }
    red[tid] = acc;
    __syncthreads();
    if (tid < 128) gs[tid] = (red[tid] + red[tid+128] + red[tid+256] + red[tid+384]) * (1.0f / PN);
    __syncthreads();
    if (tid < 128) {
        float e = b_inter[tid];
        for (int k = 0; k < 128; k++) e = fmaf(gs[k], W_inter[k*128 + tid], e);
        emb[tid] = e;
    }
    __syncthreads();
    if (tid < OUTD) {
        float o = b_out[tid];
        for (int k = 0; k < 128; k++) o = fmaf(emb[k], W_out[k*OUTD + tid], o);
        out[g*OUTD + tid] = o;
    }
}

// ---------------------------------------------------------------------------
extern "C" void kernel_launch(void* const* d_in, const int* in_sizes, int n_in,
                              void* d_out, int out_size) {
    const float* x_feat    = (const float*)d_in[0];
    const float* edge_attr = (const float*)d_in[1];
    const float* W_atom    = (const float*)d_in[2];
    const float* b_atom    = (const float*)d_in[3];
    const float* W_score   = (const float*)d_in[4];
    const float* W_edge    = (const float*)d_in[5];
    const float* W_b2c     = (const float*)d_in[6];
    const float* W_bb      = (const float*)d_in[7];
    const float* W_bc      = (const float*)d_in[8];
    const float* W_cb      = (const float*)d_in[9];
    const float* W_cc      = (const float*)d_in[10];
    const float* W_sb      = (const float*)d_in[11];
    const float* W_sc      = (const float*)d_in[12];
    const float* W_inter   = (const float*)d_in[13];
    const float* b_inter   = (const float*)d_in[14];
    const float* W_out     = (const float*)d_in[15];
    const float* b_out     = (const float*)d_in[16];
    const int*   edge_index= (const int*)d_in[17];
    float* out = (float*)d_out;

    cudaFuncSetAttribute(gemm128, cudaFuncAttributeMaxDynamicSharedMemorySize, 95000);
    cudaFuncSetAttribute(graph_kernel, cudaFuncAttributeMaxDynamicSharedMemorySize, 92000);

    void *px_, *ph_, *pxf_, *pea_, *pZ_, *pdeg_;
    void *pWab_, *pWasb_, *pWawbb_, *pW3_, *pbh_, *pbz_, *pbabb_;
    cudaGetSymbolAddress(&px_,  g_x);
    cudaGetSymbolAddress(&ph_,  g_h);
    cudaGetSymbolAddress(&pxf_, g_aggxf);
    cudaGetSymbolAddress(&pea_, g_aggea);
    cudaGetSymbolAddress(&pZ_,  g_Z);
    cudaGetSymbolAddress(&pdeg_, g_deg);
    cudaGetSymbolAddress(&pWab_, g_Wab);
    cudaGetSymbolAddress(&pWasb_, g_Wasb);
    cudaGetSymbolAddress(&pWawbb_, g_Wawbb);
    cudaGetSymbolAddress(&pW3_, g_W3);
    cudaGetSymbolAddress(&pbh_, g_biash);
    cudaGetSymbolAddress(&pbz_, g_biasz);
    cudaGetSymbolAddress(&pbabb_, g_babb);
    float* px    = (float*)px_;
    float* ph    = (float*)ph_;
    float* paxf  = (float*)pxf_;
    float* pea   = (float*)pea_;
    float* pZ    = (float*)pZ_;
    float* pdeg  = (float*)pdeg_;
    float* pWab  = (float*)pWab_;
    float* pWasb = (float*)pWasb_;
    float* pWawbb= (float*)pWawbb_;
    float* pW3   = (float*)pW3_;
    float* pbh   = (float*)pbh_;
    float* pbz   = (float*)pbz_;
    float* pbabb = (float*)pbabb_;

    const size_t smA = 128*17*8;   // 17408 (packed u64 A tile)

    // 1. fused weights (parallel)
    prep_big<<<212, 128>>>(W_atom, b_atom, W_b2c, W_sb, W_bb, W_edge, W_score);
    // 2. x = x_feat @ W_atom + b_atom          (K=64)
    gemm128<<<NN/128, 256, 64*512 + smA>>>(
        x_feat, W_atom, 64, nullptr, nullptr, 0, nullptr, nullptr, 0,
        b_atom, nullptr, nullptr, 0, px);
    // 3. nm (scores from x_feat via fused Was)
    nm_kernel<<<NN/64, 256>>>(x_feat);
    // 4. h = relu(x_feat @ Wab + biash)        (K=64)
    gemm128<<<NN/128, 256, 64*512 + smA>>>(
        x_feat, pWab, 64, nullptr, nullptr, 0, nullptr, nullptr, 0,
        pbh, nullptr, nullptr, 1, ph);
    // 5. per-graph fused pass (512 threads)
    graph_kernel<<<NG, 512, 91300>>>(px, ph, x_feat, edge_attr, edge_index);
    // 6. max for Wcc normalization
    maxred_kernel<<<1, 256>>>();
    // 7. h_cent + hcw
    hcent_kernel<<<2*NG, 128>>>(W_edge, W_bc, W_cc, W_sc, W_cb);
    // 8. Z = aggxf@Wawbb + xf@Wasb + aggea@W3 + biasz + deg*babb   (K=144)
    gemm128<<<NN/128, 256, (64+64+16)*512 + smA>>>(
        paxf, pWawbb, 64, x_feat, pWasb, 64, pea, pW3, 16,
        pbz, pdeg, pbabb, 0, pZ);
    // 9. fused Y + relu + mean + pool + heads
    final_kernel<<<NG, 512>>>(W_inter, b_inter, W_out, b_out, out);
}

// round 8
// speedup vs baseline: 3.8032x; 1.3625x over previous
#include <cuda_runtime.h>
#include <math.h>

#define NG   128
#define PN   256
#define EPG  1024
#define NN   (NG*PN)     // 32768
#define NE   (NG*EPG)    // 131072
#define DD   128
#define OUTD 10

// ---------------- device scratch ----------------
__device__ float g_x[NN*DD];
__device__ float g_h[NN*DD];
__device__ float g_nm[8*NN];              // [(r*4+c)*NN + n]
__device__ float g_aggxf[NN*64];
__device__ float g_deg[NN];
__device__ float g_aggea[NN*16];
__device__ float g_numh[2*NG*4*DD];
__device__ float g_aggbc[2*NG*4*DD];
__device__ float g_den[2*NG*4];
__device__ float g_numea[2*NG*4*16];
__device__ float g_Wccraw[2*NG*16];
__device__ unsigned int g_maxbits;
__device__ float g_hcw[2*NG*4*DD];
__device__ float g_Z[NN*DD];
// fused weights
__device__ float g_Wab[64*128];           // Wa@W_b2c
__device__ float g_Wasb[64*128];          // Wa@W_sb
__device__ float g_Wawbb[64*128];         // Wa@W_bb
__device__ float g_W3[16*128];            // We@W_bb
__device__ float g_biash[128];            // ba@W_b2c
__device__ float g_biasz[128];            // ba@W_sb
__device__ float g_babb[128];             // ba@W_bb
__device__ float g_Was[64*8];             // Wa@W_score
__device__ float g_bs[8];                 // ba@W_score

// ---------------- packed f32x2 helpers ----------------
typedef unsigned long long u64t;
__device__ __forceinline__ u64t pk2(float lo, float hi) {
    u64t r; asm("mov.b64 %0, {%1,%2};" : "=l"(r) : "f"(lo), "f"(hi)); return r;
}
__device__ __forceinline__ void upk2(u64t v, float& lo, float& hi) {
    asm("mov.b64 {%0,%1}, %2;" : "=f"(lo), "=f"(hi) : "l"(v));
}
__device__ __forceinline__ void fma2(u64t& d, u64t a, u64t b) {
    asm("fma.rn.f32x2 %0, %1, %2, %0;" : "+l"(d) : "l"(a), "l"(b));
}

// ---------------------------------------------------------------------------
// GEMM body (device fn): 128 rows x 128 cols per block, 256 threads.
// ---------------------------------------------------------------------------
__device__ __forceinline__ void mma_pass2(const float* __restrict__ A, int K,
                                          const float* __restrict__ Ws,
                                          u64t* As, int row0, int tid,
                                          int tr, int tc2, u64t acc[8][4]) {
    float4 pre[2];
#pragma unroll
    for (int it = 0; it < 2; it++) {
        int idx = tid + it*256; int lr = idx >> 2, lc = (idx & 3) * 4;
        pre[it] = *(const float4*)(A + (size_t)(row0 + lr)*K + lc);
    }
    for (int k0 = 0; k0 < K; k0 += 16) {
        __syncthreads();
#pragma unroll
        for (int it = 0; it < 2; it++) {
            int idx = tid + it*256; int lr = idx >> 2, lc = (idx & 3) * 4;
            float4 v = pre[it];
            As[lr*17 + lc + 0] = pk2(v.x, v.x);
            As[lr*17 + lc + 1] = pk2(v.y, v.y);
            As[lr*17 + lc + 2] = pk2(v.z, v.z);
            As[lr*17 + lc + 3] = pk2(v.w, v.w);
        }
        __syncthreads();
        if (k0 + 16 < K) {
#pragma unroll
            for (int it = 0; it < 2; it++) {
                int idx = tid + it*256; int lr = idx >> 2, lc = (idx & 3) * 4;
                pre[it] = *(const float4*)(A + (size_t)(row0 + lr)*K + k0 + 16 + lc);
            }
        }
#pragma unroll
        for (int kk = 0; kk < 16; kk++) {
            const float* wrow = Ws + (k0 + kk)*128;
            u64t wv[4];
#pragma unroll
            for (int jp = 0; jp < 4; jp++)
                wv[jp] = *(const u64t*)(wrow + tc2 + 32*jp);
#pragma unroll
            for (int i = 0; i < 8; i++) {
                u64t ap = As[(tr + 16*i)*17 + kk];
#pragma unroll
                for (int jp = 0; jp < 4; jp++) fma2(acc[i][jp], ap, wv[jp]);
            }
        }
    }
}

__device__ __forceinline__ void gemm_body(
        const float* __restrict__ A1, const float* __restrict__ W1, int K1,
        const float* __restrict__ A2, const float* __restrict__ W2, int K2,
        const float* __restrict__ A3, const float* __restrict__ W3, int K3,
        const float* __restrict__ bias,
        const float* __restrict__ rowscale,
        const float* __restrict__ rowvec,
        int relu_flag, float* __restrict__ out,
        int blk, float* sm) {
    float* Ws1 = sm;
    float* Ws2 = Ws1 + K1*128;
    float* Ws3 = Ws2 + K2*128;
    u64t*  As  = (u64t*)(Ws3 + K3*128);

    const int tid = threadIdx.x;
    const int tr = tid >> 4, tc2 = (tid & 15) * 2;
    const int row0 = blk * 128;

    for (int i = tid*4; i < K1*128; i += 1024) *(float4*)(Ws1+i) = *(const float4*)(W1+i);
    if (A2) for (int i = tid*4; i < K2*128; i += 1024) *(float4*)(Ws2+i) = *(const float4*)(W2+i);
    if (A3) for (int i = tid*4; i < K3*128; i += 1024) *(float4*)(Ws3+i) = *(const float4*)(W3+i);

    u64t acc[8][4];
#pragma unroll
    for (int i = 0; i < 8; i++)
#pragma unroll
        for (int j = 0; j < 4; j++) acc[i][j] = 0ull;

    mma_pass2(A1, K1, Ws1, As, row0, tid, tr, tc2, acc);
    if (A2) mma_pass2(A2, K2, Ws2, As, row0, tid, tr, tc2, acc);
    if (A3) mma_pass2(A3, K3, Ws3, As, row0, tid, tr, tc2, acc);

#pragma unroll
    for (int i = 0; i < 8; i++) {
        int row = row0 + tr + 16*i;
        float rs = rowscale ? rowscale[row] : 0.f;
#pragma unroll
        for (int jp = 0; jp < 4; jp++) {
            int cb = tc2 + 32*jp;
            float lo, hi; upk2(acc[i][jp], lo, hi);
            if (bias)   { lo += bias[cb];        hi += bias[cb+1]; }
            if (rowvec) { lo += rs * rowvec[cb]; hi += rs * rowvec[cb+1]; }
            if (relu_flag) { lo = fmaxf(lo, 0.f); hi = fmaxf(hi, 0.f); }
            out[(size_t)row*128 + cb]     = lo;
            out[(size_t)row*128 + cb + 1] = hi;
        }
    }
}

// ---------------------------------------------------------------------------
// nm body: scores = xf@Was + bs, softmax over centroids. 64 nodes, 256 thr.
// ---------------------------------------------------------------------------
__device__ __forceinline__ void nm_body(const float* __restrict__ xf, int n0,
                                        float* sm) {
    float* xs  = sm;            // 64*65
    float* ss  = xs + 64*65;    // 512
    float* Ws  = ss + 512;      // 512
    float* bss = Ws + 512;      // 8
    int tid = threadIdx.x;

    for (int i = tid; i < 64*64; i += 256) {
        int rw = i >> 6, k = i & 63;
        xs[rw*65 + k] = xf[(size_t)(n0 + rw)*64 + k];
    }
    for (int i = tid; i < 64*8; i += 256) Ws[i] = g_Was[i];
    if (tid < 8) bss[tid] = g_bs[tid];
    __syncthreads();

    int node = tid >> 2, q = tid & 3;
    float s0 = bss[q], s1 = bss[q + 4];
    for (int k = 0; k < 64; k++) {
        float a = xs[node*65 + k];
        s0 = fmaf(a, Ws[k*8 + q], s0);
        s1 = fmaf(a, Ws[k*8 + q + 4], s1);
    }
    ss[node*8 + q]     = s0;
    ss[node*8 + q + 4] = s1;
    __syncthreads();

    if (tid < 128) {
        int nd = tid >> 1, r = tid & 1;
        float v[4];
#pragma unroll
        for (int c = 0; c < 4; c++) v[c] = ss[nd*8 + c*2 + r];
        float m = fmaxf(fmaxf(v[0], v[1]), fmaxf(v[2], v[3]));
        float e[4], sum = 0.f;
#pragma unroll
        for (int c = 0; c < 4; c++) { e[c] = expf(v[c] - m); sum += e[c]; }
        float inv = 1.f / sum;
        int n = n0 + nd;
#pragma unroll
        for (int c = 0; c < 4; c++)
            g_nm[(size_t)(r*4 + c)*NN + n] = e[c] * inv;
    }
}

// ---------------------------------------------------------------------------
// hcent body, 256 threads: thread = (d, half); half owns centroids {2h,2h+1}
// ---------------------------------------------------------------------------
__device__ __forceinline__ void hcent_body(
        const float* __restrict__ Wedge, const float* __restrict__ Wbc,
        const float* __restrict__ Wcc_,  const float* __restrict__ Wsc,
        const float* __restrict__ Wcb, int b, float* sm) {
    float* We    = sm;          // 2048
    float* cx    = We + 2048;   // 512
    float* bc    = cx + 512;    // 512
    float* cc    = bc + 512;    // 512
    float* hc    = cc + 512;    // 512
    float* numea = hc + 512;    // 64
    float* Wg    = numea + 64;  // 16
    float* den   = Wg + 16;     // 4

    int tid = threadIdx.x;
    int d = tid & 127, half = tid >> 7;
    size_t base = (size_t)b * 512;
    float maxplus = __uint_as_float(g_maxbits) + 1e-9f;

    for (int i = tid; i < 2048; i += 256) We[i] = Wedge[i];
    for (int i = tid; i < 512; i += 256) {
        cx[i] = g_numh[base + i];
        bc[i] = g_aggbc[base + i];
    }
    if (tid < 64) numea[tid] = g_numea[(size_t)b*64 + tid];
    if (tid < 16) Wg[tid] = g_Wccraw[b*16 + tid] / maxplus;
    if (tid < 4)  den[tid] = g_den[(size_t)b*4 + tid];
    __syncthreads();

#pragma unroll
    for (int cl = 0; cl < 2; cl++) {
        int c = half*2 + cl;
        float v = cx[c*128 + d];
#pragma unroll
        for (int q = 0; q < 16; q++)
            v = fmaf(numea[c*16 + q], We[q*128 + d], v);
        cx[c*128 + d] = v / den[c];
    }
    __syncthreads();
#pragma unroll
    for (int cl = 0; cl < 2; cl++) {
        int c = half*2 + cl;
        float a = 0.f;
#pragma unroll
        for (int j = 0; j < 4; j++) a = fmaf(Wg[c*4 + j], cx[j*128 + d], a);
        cc[c*128 + d] = a;
    }
    __syncthreads();
    {
        float acc[2] = {0.f, 0.f};
        for (int k = 0; k < 128; k++) {
            float wb = Wbc[k*128 + d], wc = Wcc_[k*128 + d], ws = Wsc[k*128 + d];
#pragma unroll
            for (int cl = 0; cl < 2; cl++) {
                int c = half*2 + cl;
                acc[cl] = fmaf(bc[c*128 + k], wb, acc[cl]);
                acc[cl] = fmaf(cc[c*128 + k], wc, acc[cl]);
                acc[cl] = fmaf(cx[c*128 + k], ws, acc[cl]);
            }
        }
#pragma unroll
        for (int cl = 0; cl < 2; cl++)
            hc[(half*2 + cl)*128 + d] = fmaxf(acc[cl], 0.f);
    }
    __syncthreads();
    {
        float o[2] = {0.f, 0.f};
        for (int k = 0; k < 128; k++) {
            float w = Wcb[k*128 + d];
#pragma unroll
            for (int cl = 0; cl < 2; cl++)
                o[cl] = fmaf(hc[(half*2 + cl)*128 + k], w, o[cl]);
        }
#pragma unroll
        for (int cl = 0; cl < 2; cl++)
            g_hcw[base + (half*2 + cl)*128 + d] = o[cl];
    }
}

// ---------------------------------------------------------------------------
// MEGA1: blocks 0-255 x-GEMM, 256-511 h-GEMM, 512-1023 nm.
// ---------------------------------------------------------------------------
__global__ void __launch_bounds__(256, 2)
mega1(const float* __restrict__ x_feat,
      const float* __restrict__ W_atom, const float* __restrict__ b_atom) {
    extern __shared__ float sm[];
    int b = blockIdx.x;
    if (b < 256) {
        gemm_body(x_feat, W_atom, 64, nullptr, nullptr, 0, nullptr, nullptr, 0,
                  b_atom, nullptr, nullptr, 0, g_x, b, sm);
    } else if (b < 512) {
        gemm_body(x_feat, g_Wab, 64, nullptr, nullptr, 0, nullptr, nullptr, 0,
                  g_biash, nullptr, nullptr, 1, g_h, b - 256, sm);
    } else {
        nm_body(x_feat, (b - 512) * 64, sm);
    }
}

// ---------------------------------------------------------------------------
// MEGA2: blocks 0-255 Z-GEMM (K=144), 256-511 hcent.
// ---------------------------------------------------------------------------
__global__ void __launch_bounds__(256, 2)
mega2(const float* __restrict__ x_feat,
      const float* __restrict__ Wedge, const float* __restrict__ Wbc,
      const float* __restrict__ Wcc_,  const float* __restrict__ Wsc,
      const float* __restrict__ Wcb) {
    extern __shared__ float sm[];
    int b = blockIdx.x;
    if (b < 256) {
        gemm_body(g_aggxf, g_Wawbb, 64, x_feat, g_Wasb, 64, g_aggea, g_W3, 16,
                  g_biasz, g_deg, g_babb, 0, g_Z, b, sm);
    } else {
        hcent_body(Wedge, Wbc, Wcc_, Wsc, Wcb, b - 256, sm);
    }
}

// ---------------------------------------------------------------------------
// Parallel weight precompute + g_maxbits reset.  grid = 212 x 128.
// ---------------------------------------------------------------------------
__global__ void prep_big(const float* __restrict__ Wa, const float* __restrict__ ba,
                         const float* __restrict__ Wb2c, const float* __restrict__ Wsb,
                         const float* __restrict__ Wbb, const float* __restrict__ We,
                         const float* __restrict__ Wscore) {
    int b = blockIdx.x, d = threadIdx.x;
    if (b < 64) {
        float a = 0.f;
        for (int k = 0; k < 128; k++) a = fmaf(Wa[b*128+k], Wb2c[k*128+d], a);
        g_Wab[b*128+d] = a;
    } else if (b < 128) {
        int f = b - 64; float a = 0.f;
        for (int k = 0; k < 128; k++) a = fmaf(Wa[f*128+k], Wsb[k*128+d], a);
        g_Wasb[f*128+d] = a;
    } else if (b < 144) {
        int q = b - 128; float a = 0.f;
        for (int k = 0; k < 128; k++) a = fmaf(We[q*128+k], Wbb[k*128+d], a);
        g_W3[q*128+d] = a;
    } else if (b < 208) {
        int f = b - 144; float a = 0.f;
        for (int k = 0; k < 128; k++) a = fmaf(Wa[f*128+k], Wbb[k*128+d], a);
        g_Wawbb[f*128+d] = a;
    } else if (b == 208) {
        float a = 0.f;
        for (int k = 0; k < 128; k++) a = fmaf(ba[k], Wb2c[k*128+d], a);
        g_biash[d] = a;
    } else if (b == 209) {
        float a = 0.f;
        for (int k = 0; k < 128; k++) a = fmaf(ba[k], Wsb[k*128+d], a);
        g_biasz[d] = a;
    } else if (b == 210) {
        float a = 0.f;
        for (int k = 0; k < 128; k++) a = fmaf(ba[k], Wbb[k*128+d], a);
        g_babb[d] = a;
        if (d == 0) g_maxbits = 0u;
    } else {
        for (int o = d; o < 520; o += 128) {
            int r = o >> 3, q = o & 7;
            const float* L = (r < 64) ? (Wa + r*128) : ba;
            float a = 0.f;
            for (int k = 0; k < 128; k++) a = fmaf(L[k], Wscore[k*8+q], a);
            if (r < 64) g_Was[r*8+q] = a; else g_bs[q] = a;
        }
    }
}

// ---------------------------------------------------------------------------
// Per-graph fused kernel.  1 block / graph, 1024 threads, one edge / thread.
// Reads g_x / g_h / g_nm device globals directly (NOT via host pointers).
// ---------------------------------------------------------------------------
__global__ void __launch_bounds__(1024)
graph_kernel(const float* __restrict__ xf,
             const float* __restrict__ edge_attr,
             const int* __restrict__ ei) {
    extern __shared__ float smf[];
    float* nm_sm   = smf;              // 2048
    float* srcw    = nm_sm + 2048;     // 2048
    float* ea_sm   = srcw + 2048;      // 16384
    float* wnum_c  = ea_sm + 16384;    // 8192
    float* numh_sm = wnum_c + 8192;    // 1024
    float* bc_sm   = numh_sm + 1024;   // 1024
    float* red_sm  = bc_sm + 1024;     // 1024
    float* w_sm    = red_sm + 1024;    // 24
    float* den_sm  = w_sm + 24;        // 8
    int* sl  = (int*)(den_sm + 8);     // 1024
    int* dl  = sl + 1024;              // 1024
    int* deg = dl + 1024;              // 256
    int* off = deg + 256;              // 257
    int* cur = off + 257;              // 256
    int* csr = cur + 256;              // 1024

    const int g = blockIdx.x;
    const int tid = threadIdx.x;
    const int gb = g * PN;
    const int ge = g * EPG;

    if (tid < PN) deg[tid] = 0;
    if (tid < 20) w_sm[tid] = 0.f;
    for (int i = tid; i < 2048; i += 1024) {
        srcw[i] = 0.f;
        nm_sm[i] = g_nm[(size_t)(i >> 8)*NN + gb + (i & 255)];
    }
    __syncthreads();

    // ---- edge pass: one edge per thread ----
    float wp[20];
    {
        const int e = tid;
        int s = ei[ge + e] - gb;
        int d = ei[NE + ge + e] - gb;
        sl[e] = s; dl[e] = d;
        atomicAdd(&deg[d], 1);
        const float4* earow = (const float4*)(edge_attr + (size_t)(ge + e)*16);
        float4* eadst = (float4*)(ea_sm + e*16);
        eadst[0] = earow[0]; eadst[1] = earow[1];
        eadst[2] = earow[2]; eadst[3] = earow[3];

        float ns[8], nd[8];
#pragma unroll
        for (int rc = 0; rc < 8; rc++) {
            ns[rc] = nm_sm[rc*256 + s];
            nd[rc] = nm_sm[rc*256 + d];
            float wv = nd[rc]*nd[rc]*ns[rc];
            wnum_c[e*8 + rc] = wv;
            atomicAdd(&srcw[rc*256 + s], wv);
        }
#pragma unroll
        for (int r = 0; r < 2; r++) {
            int b = r*4, w0 = r*10;
            wp[w0+0] = ns[b+0]*nd[b+1];
            wp[w0+1] = ns[b+0]*nd[b+2];
            wp[w0+2] = ns[b+0]*nd[b+3];
            wp[w0+3] = ns[b+1]*nd[b+2];
            wp[w0+4] = ns[b+1]*nd[b+3];
            wp[w0+5] = ns[b+2]*nd[b+3];
#pragma unroll
            for (int c = 0; c < 4; c++) wp[w0+6+c] = ns[b+c]*nd[b+c];
        }
    }
#pragma unroll
    for (int p = 0; p < 20; p++)
        for (int o = 16; o > 0; o >>= 1)
            wp[p] += __shfl_down_sync(0xffffffffu, wp[p], o);
    if ((tid & 31) == 0)
#pragma unroll
        for (int p = 0; p < 20; p++) atomicAdd(&w_sm[p], wp[p]);
    __syncthreads();

    // ---- numea partials ----
    {
        const int eh = tid >> 7, rcb = (tid >> 4) & 7, qb = tid & 15;
        float nacc = 0.f;
        for (int el = eh*128; el < eh*128 + 128; el++)
            nacc = fmaf(wnum_c[el*8 + rcb], ea_sm[el*16 + qb], nacc);
        red_sm[tid] = nacc;
    }
    __syncthreads();
    if (tid < 256) {
        int rc = tid >> 5, lane = tid & 31;
        float s = 0.f;
        for (int n = lane; n < PN; n += 32) s += nm_sm[rc*256 + n];
        for (int o = 16; o > 0; o >>= 1) s += __shfl_down_sync(0xffffffffu, s, o);
        if (lane == 0) den_sm[rc] = s + 1e-6f;
    }
    if (tid >= 512 && tid < 640) {
        int t = tid - 512;
        float v = 0.f;
#pragma unroll
        for (int j = 0; j < 8; j++) v += red_sm[t + j*128];
        int rc = t >> 4, q = t & 15;
        int r = rc >> 2, c = rc & 3;
        g_numea[((size_t)(r*NG + g)*4 + c)*16 + q] = v;
    }

    // ---- CSR scan (warp 0) ----
    if (tid < 32) {
        int run = 0;
        for (int seg = 0; seg < 8; seg++) {
            int dv = deg[seg*32 + tid];
            int v = dv;
#pragma unroll
            for (int o = 1; o < 32; o <<= 1) {
                int t = __shfl_up_sync(0xffffffffu, v, o);
                if ((tid & 31) >= o) v += t;
            }
            off[seg*32 + tid] = run + v - dv;
            run += __shfl_sync(0xffffffffu, v, 31);
        }
        if (tid == 31) off[PN] = run;
    }
    __syncthreads();
    if (tid < PN) cur[tid] = off[tid];
    __syncthreads();
    {
        int pos = atomicAdd(&cur[dl[tid]], 1);
        csr[pos] = tid;
    }
    __syncthreads();

    if (tid < PN) g_deg[gb + tid] = (float)deg[tid];

    for (int i = tid; i < PN*16; i += 1024) {
        int nl = i >> 4, q = i & 15;
        float a = 0.f;
        int e0 = off[nl], e1 = off[nl + 1];
        for (int ii = e0; ii < e1; ii++)
            a += ea_sm[csr[ii]*16 + q];
        g_aggea[(size_t)(gb + nl)*16 + q] = a;
    }

    {
        const int d64 = tid & 63, grp = tid >> 6;
        for (int nl = grp; nl < PN; nl += 16) {
            float a = 0.f;
            int e0 = off[nl], e1 = off[nl + 1];
            for (int ii = e0; ii < e1; ii++)
                a += xf[(size_t)(gb + sl[csr[ii]])*64 + d64];
            g_aggxf[(size_t)(gb + nl)*64 + d64] = a;
        }
    }

    // ---- vector phase ----
    const int d = tid & 127, grp8 = tid >> 7;
    float numa[8], bca[8];
#pragma unroll
    for (int rc = 0; rc < 8; rc++) { numa[rc] = 0.f; bca[rc] = 0.f; }

    for (int nl = grp8; nl < PN; nl += 8) {
        float xv = g_x[(size_t)(gb + nl)*128 + d];
        float hv = g_h[(size_t)(gb + nl)*128 + d];
#pragma unroll
        for (int rc = 0; rc < 8; rc++) {
            float w1 = nm_sm[rc*256 + nl];
            numa[rc] = fmaf(w1 + srcw[rc*256 + nl], hv, numa[rc]);
            bca[rc]  = fmaf(w1, xv, bca[rc]);
        }
    }
    __syncthreads();
    for (int gg = 0; gg < 8; gg++) {
        if (grp8 == gg) {
            if (gg == 0)
#pragma unroll
                for (int rc = 0; rc < 8; rc++) {
                    numh_sm[rc*128 + d] = numa[rc];
                    bc_sm[rc*128 + d]   = bca[rc];
                }
            else
#pragma unroll
                for (int rc = 0; rc < 8; rc++) {
                    numh_sm[rc*128 + d] += numa[rc];
                    bc_sm[rc*128 + d]   += bca[rc];
                }
        }
        __syncthreads();
    }

    for (int i = tid; i < 8*128; i += 1024) {
        int rc = i >> 7, dd = i & 127;
        int r = rc >> 2, c = rc & 3;
        size_t o = ((size_t)(r*NG + g)*4 + c)*128 + dd;
        g_numh[o]  = numh_sm[rc*128 + dd];
        g_aggbc[o] = bc_sm[rc*128 + dd];
    }
    if (tid < 8) {
        int r = tid >> 2, c = tid & 3;
        g_den[(size_t)(r*NG + g)*4 + c] = den_sm[tid];
    }

    if (tid < 32) {
        const int pidx[4][4] = { {6,0,1,2}, {0,7,3,4}, {1,3,8,5}, {2,4,5,9} };
        int r = tid >> 4, idx = tid & 15;
        int i = idx >> 2, j = idx & 3;
        float v = w_sm[r*10 + pidx[i][j]];
        if (i == j) v *= 0.5f;
        g_Wccraw[(r*NG + g)*16 + idx] = v;
        float m = v;
        for (int o = 16; o > 0; o >>= 1)
            m = fmaxf(m, __shfl_down_sync(0xffffffffu, m, o));
        if (tid == 0) atomicMax(&g_maxbits, __float_as_uint(m));
    }
}

// ---------------------------------------------------------------------------
// Final fused: node = mean_r relu(Z + Sum_c nm*hcw); pool; heads.  grid = NG
// ---------------------------------------------------------------------------
__global__ void final_kernel(const float* __restrict__ W_inter,
                             const float* __restrict__ b_inter,
                             const float* __restrict__ W_out,
                             const float* __restrict__ b_out,
                             float* __restrict__ out) {
    __shared__ float hcw[1024], nm_s[2048], red[512], gs[128], emb[128];
    int g = blockIdx.x, tid = threadIdx.x;
    for (int i = tid; i < 1024; i += 512) {
        int r = i >> 9;
        hcw[i] = g_hcw[(size_t)(r*NG + g)*512 + (i & 511)];
    }
    for (int i = tid; i < 2048; i += 512)
        nm_s[i] = g_nm[(size_t)(i >> 8)*NN + g*PN + (i & 255)];
    __syncthreads();

    int d = tid & 127, q4 = tid >> 7;
    float acc = 0.f;
    for (int nl = q4; nl < PN; nl += 4) {
        float z = g_Z[(size_t)(g*PN + nl)*128 + d];
        float y0 = 0.f, y1 = 0.f;
#pragma unroll
        for (int c = 0; c < 4; c++) {
            y0 = fmaf(nm_s[c*256 + nl],       hcw[c*128 + d],       y0);
            y1 = fmaf(nm_s[(4 + c)*256 + nl], hcw[512 + c*128 + d], y1);
        }
        acc += 0.5f * (fmaxf(z + y0, 0.f) + fmaxf(z + y1, 0.f));
    }
    red[tid] = acc;
    __syncthreads();
    if (tid < 128) gs[tid] = (red[tid] + red[tid+128] + red[tid+256] + red[tid+384]) * (1.0f / PN);
    __syncthreads();
    if (tid < 128) {
        float e = b_inter[tid];
        for (int k = 0; k < 128; k++) e = fmaf(gs[k], W_inter[k*128 + tid], e);
        emb[tid] = e;
    }
    __syncthreads();
    if (tid < OUTD) {
        float o = b_out[tid];
        for (int k = 0; k < 128; k++) o = fmaf(emb[k], W_out[k*OUTD + tid], o);
        out[g*OUTD + tid] = o;
    }
}

// ---------------------------------------------------------------------------
extern "C" void kernel_launch(void* const* d_in, const int* in_sizes, int n_in,
                              void* d_out, int out_size) {
    const float* x_feat    = (const float*)d_in[0];
    const float* edge_attr = (const float*)d_in[1];
    const float* W_atom    = (const float*)d_in[2];
    const float* b_atom    = (const float*)d_in[3];
    const float* W_score   = (const float*)d_in[4];
    const float* W_edge    = (const float*)d_in[5];
    const float* W_b2c     = (const float*)d_in[6];
    const float* W_bb      = (const float*)d_in[7];
    const float* W_bc      = (const float*)d_in[8];
    const float* W_cb      = (const float*)d_in[9];
    const float* W_cc      = (const float*)d_in[10];
    const float* W_sb      = (const float*)d_in[11];
    const float* W_sc      = (const float*)d_in[12];
    const float* W_inter   = (const float*)d_in[13];
    const float* b_inter   = (const float*)d_in[14];
    const float* W_out     = (const float*)d_in[15];
    const float* b_out     = (const float*)d_in[16];
    const int*   edge_index= (const int*)d_in[17];
    float* out = (float*)d_out;

    cudaFuncSetAttribute(mega1, cudaFuncAttributeMaxDynamicSharedMemorySize, 52000);
    cudaFuncSetAttribute(mega2, cudaFuncAttributeMaxDynamicSharedMemorySize, 95000);
    cudaFuncSetAttribute(graph_kernel, cudaFuncAttributeMaxDynamicSharedMemorySize, 145000);

    const size_t smA = 128*17*8;   // packed u64 A tile = 17408

    // 1. fused weights
    prep_big<<<212, 128>>>(W_atom, b_atom, W_b2c, W_sb, W_bb, W_edge, W_score);
    // 2. x-GEMM + h-GEMM + nm in one launch
    mega1<<<1024, 256, 64*512 + smA>>>(x_feat, W_atom, b_atom);
    // 3. per-graph fused pass (reads g_x/g_h/g_nm directly)
    graph_kernel<<<NG, 1024, 142468>>>(x_feat, edge_attr, edge_index);
    // 4. Z-GEMM + hcent in one launch
    mega2<<<512, 256, (64+64+16)*512 + smA>>>(x_feat, W_edge, W_bc, W_cc, W_sc, W_cb);
    // 5. fused Y + relu + mean + pool + heads
    final_kernel<<<NG, 512>>>(W_inter, b_inter, W_out, b_out, out);
}